// round 15
// baseline (speedup 1.0000x reference)
#include <cuda_runtime.h>
#include <cuda_bf16.h>
#include <cstdint>

#define NN 50000
#define EE 800000
#define HH 128
#define INCH 64
#define LL 4
#define K1 258

// word strides (uint32 units)
#define LDX 132   // node sX: 264 bf16/row
#define LDT 68    // sT / pre sX: 136 bf16/row
#define LDB 20    // sW: 40 bf16/row

// ================= scratch (__device__ globals; no allocation) =================
__device__ float g_h[(size_t)NN * HH];
__device__ float g_coords[(size_t)NN * 3];
__device__ float g_aggF[(size_t)NN * HH];
__device__ float g_aggC[(size_t)NN * 3];
__device__ float g_cnt[NN];
__device__ float g_P1[(size_t)NN * HH];
__device__ float g_P2[(size_t)NN * HH];
// pre-transposed + bf16-split weights: [L][n=128][k]
__device__ __align__(16) __nv_bfloat16 g_eW1hi[(size_t)LL * 128 * 256];
__device__ __align__(16) __nv_bfloat16 g_eW1lo[(size_t)LL * 128 * 256];
__device__ __align__(16) __nv_bfloat16 g_eW2hi[(size_t)LL * 128 * 128];
__device__ __align__(16) __nv_bfloat16 g_eW2lo[(size_t)LL * 128 * 128];
__device__ __align__(16) __nv_bfloat16 g_cW1hi[(size_t)LL * 128 * 128];
__device__ __align__(16) __nv_bfloat16 g_cW1lo[(size_t)LL * 128 * 128];
__device__ __align__(16) __nv_bfloat16 g_nW1hi[(size_t)LL * 128 * 256];
__device__ __align__(16) __nv_bfloat16 g_nW1lo[(size_t)LL * 128 * 256];
__device__ __align__(16) __nv_bfloat16 g_nW2hi[(size_t)LL * 128 * 128];
__device__ __align__(16) __nv_bfloat16 g_nW2lo[(size_t)LL * 128 * 128];

__device__ __forceinline__ float silu_f(float x) {
    return x * __fdividef(1.f, 1.f + __expf(-x));
}

__device__ __forceinline__ uint32_t bf16pack(float f0, float f1) {
    uint32_t d;
    asm("cvt.rn.bf16x2.f32 %0, %1, %2;" : "=r"(d) : "f"(f1), "f"(f0));
    return d;
}
__device__ __forceinline__ void split2(float f0, float f1, uint32_t& h2, uint32_t& l2) {
    h2 = bf16pack(f0, f1);
    float h0 = __uint_as_float(h2 << 16);
    float h1 = __uint_as_float(h2 & 0xffff0000u);
    l2 = bf16pack(f0 - h0, f1 - h1);
}

__device__ __forceinline__ void cp_async16(uint32_t dst, const void* src) {
    asm volatile("cp.async.ca.shared.global [%0], [%1], 16;" :: "r"(dst), "l"(src));
}
#define CP_COMMIT() asm volatile("cp.async.commit_group;" ::: "memory")
#define CP_WAIT0()  asm volatile("cp.async.wait_group 0;" ::: "memory")

__device__ __forceinline__ void ldsm4(uint32_t* r, uint32_t addr) {
    asm volatile("ldmatrix.sync.aligned.m8n8.x4.shared.b16 {%0,%1,%2,%3}, [%4];"
                 : "=r"(r[0]), "=r"(r[1]), "=r"(r[2]), "=r"(r[3]) : "r"(addr));
}

__device__ __forceinline__ void red2(float* p, float a, float b) {
    asm volatile("red.global.add.v2.f32 [%0], {%1,%2};" :: "l"(p), "f"(a), "f"(b) : "memory");
}

#define MMA_BF16(d, a0, a1, a2, a3, b0, b1) \
    asm volatile("mma.sync.aligned.m16n8k16.row.col.f32.bf16.bf16.f32 " \
                 "{%0,%1,%2,%3}, {%4,%5,%6,%7}, {%8,%9}, {%0,%1,%2,%3};" \
                 : "+f"((d)[0]), "+f"((d)[1]), "+f"((d)[2]), "+f"((d)[3]) \
                 : "r"(a0), "r"(a1), "r"(a2), "r"(a3), "r"(b0), "r"(b1))

#define ZERO_ACC(acc) do { \
    _Pragma("unroll") for (int _r = 0; _r < 2; ++_r) \
    _Pragma("unroll") for (int _c = 0; _c < 4; ++_c) \
    _Pragma("unroll") for (int _q = 0; _q < 4; ++_q) acc[_r][_c][_q] = 0.f; } while (0)

// prestage first 32-k weight chunk (hi+lo) into sW buffer 0
__device__ __forceinline__ void prestage_w(
    const __nv_bfloat16* __restrict__ gHi, const __nv_bfloat16* __restrict__ gLo,
    int Kg, uint32_t swb, int tid)
{
    const int n = tid >> 2, seg = tid & 3;
    uint32_t dst_hi = swb + (n * LDB + seg * 4) * 4;
    cp_async16(dst_hi, gHi + (size_t)n * Kg + seg * 8);
    cp_async16(dst_hi + 2560 * 4, gLo + (size_t)n * Kg + seg * 8);
    CP_COMMIT();
}

// =================== bf16x3 warp-tiled GEMM (128 x 128, 16 warps, ldmatrix) ===================
__device__ __forceinline__ void wgemm_bf16(
    const __nv_bfloat16* __restrict__ gHi, const __nv_bfloat16* __restrict__ gLo,
    int Kg, int nch,
    const uint32_t* sInHi, const uint32_t* sInLo, int ldw,
    uint32_t* sW, int tid, float acc[2][4][4], int prestaged)
{
    const int lane = tid & 31, wid = tid >> 5;
    const int wr = wid & 3, wc = wid >> 2;
    const int n = tid >> 2, seg = tid & 3;

    uint32_t swb = (uint32_t)__cvta_generic_to_shared(sW);
    uint32_t dst_hi = swb + (n * LDB + seg * 4) * 4;
    uint32_t dst_lo = dst_hi + 2560 * 4;
    const __nv_bfloat16* src_h = gHi + (size_t)n * Kg + seg * 8;
    const __nv_bfloat16* src_l = gLo + (size_t)n * Kg + seg * 8;

    if (!prestaged) {
        cp_async16(dst_hi, src_h);
        cp_async16(dst_lo, src_l);
        CP_COMMIT();
    }
    CP_WAIT0();
    __syncthreads();

    const uint32_t aOff = (uint32_t)(wr * 32 + (lane & 15)) * (uint32_t)ldw * 4u
                        + (uint32_t)(lane >> 4) * 16u;
    const uint32_t aHi0 = (uint32_t)__cvta_generic_to_shared(sInHi) + aOff;
    const uint32_t aLo0 = (uint32_t)__cvta_generic_to_shared(sInLo) + aOff;
    const uint32_t aRf = (uint32_t)(16 * ldw * 4);
    const uint32_t bOff = (uint32_t)(wc * 32 + ((lane >> 4) << 3) + (lane & 7)) * (LDB * 4u)
                        + (uint32_t)((lane >> 3) & 1) * 16u;

    for (int c = 0; c < nch; ++c) {
        if (c + 1 < nch) {
            uint32_t off = (uint32_t)((c + 1) & 1) * (5120 * 4);
            cp_async16(dst_hi + off, src_h + (c + 1) * 32);
            cp_async16(dst_lo + off, src_l + (c + 1) * 32);
            CP_COMMIT();
        }
        uint32_t bufHiB = swb + (uint32_t)(c & 1) * (5120 * 4) + bOff;
        uint32_t bufLoB = bufHiB + 2560 * 4;
        #pragma unroll
        for (int ks = 0; ks < 2; ++ks) {
            const uint32_t ka4 = (uint32_t)(c * 16 + ks * 8) * 4u;
            uint32_t ah[2][4], al[2][4], bh[2][4], bl[2][4];
            ldsm4(ah[0], aHi0 + ka4);
            ldsm4(ah[1], aHi0 + ka4 + aRf);
            ldsm4(al[0], aLo0 + ka4);
            ldsm4(al[1], aLo0 + ka4 + aRf);
            ldsm4(bh[0], bufHiB + ks * 32);
            ldsm4(bh[1], bufHiB + ks * 32 + 16 * LDB * 4);
            ldsm4(bl[0], bufLoB + ks * 32);
            ldsm4(bl[1], bufLoB + ks * 32 + 16 * LDB * 4);
            #pragma unroll
            for (int cf = 0; cf < 4; ++cf) {
                const int p = cf >> 1, ix = (cf & 1) * 2;
                #pragma unroll
                for (int rf = 0; rf < 2; ++rf)
                    MMA_BF16(acc[rf][cf], ah[rf][0], ah[rf][1], ah[rf][2], ah[rf][3],
                             bl[p][ix], bl[p][ix + 1]);
            }
            #pragma unroll
            for (int cf = 0; cf < 4; ++cf) {
                const int p = cf >> 1, ix = (cf & 1) * 2;
                #pragma unroll
                for (int rf = 0; rf < 2; ++rf)
                    MMA_BF16(acc[rf][cf], al[rf][0], al[rf][1], al[rf][2], al[rf][3],
                             bh[p][ix], bh[p][ix + 1]);
            }
            #pragma unroll
            for (int cf = 0; cf < 4; ++cf) {
                const int p = cf >> 1, ix = (cf & 1) * 2;
                #pragma unroll
                for (int rf = 0; rf < 2; ++rf)
                    MMA_BF16(acc[rf][cf], ah[rf][0], ah[rf][1], ah[rf][2], ah[rf][3],
                             bh[p][ix], bh[p][ix + 1]);
            }
        }
        if (c + 1 < nch) CP_WAIT0();
        __syncthreads();
    }
}

// pure-bf16 single-term variant: A hi only, B hi only. D += Ah*Bh.
__device__ __forceinline__ void wgemm_bf16_1t(
    const __nv_bfloat16* __restrict__ gHi,
    int Kg, int nch,
    const uint32_t* sInHi, int ldw,
    uint32_t* sW, int tid, float acc[2][4][4])
{
    const int lane = tid & 31, wid = tid >> 5;
    const int wr = wid & 3, wc = wid >> 2;
    const int n = tid >> 2, seg = tid & 3;

    uint32_t swb = (uint32_t)__cvta_generic_to_shared(sW);
    uint32_t dst_hi = swb + (n * LDB + seg * 4) * 4;
    const __nv_bfloat16* src_h = gHi + (size_t)n * Kg + seg * 8;

    cp_async16(dst_hi, src_h);
    CP_COMMIT(); CP_WAIT0();
    __syncthreads();

    const uint32_t aOff = (uint32_t)(wr * 32 + (lane & 15)) * (uint32_t)ldw * 4u
                        + (uint32_t)(lane >> 4) * 16u;
    const uint32_t aHi0 = (uint32_t)__cvta_generic_to_shared(sInHi) + aOff;
    const uint32_t aRf = (uint32_t)(16 * ldw * 4);
    const uint32_t bOff = (uint32_t)(wc * 32 + ((lane >> 4) << 3) + (lane & 7)) * (LDB * 4u)
                        + (uint32_t)((lane >> 3) & 1) * 16u;

    for (int c = 0; c < nch; ++c) {
        if (c + 1 < nch) {
            uint32_t off = (uint32_t)((c + 1) & 1) * (5120 * 4);
            cp_async16(dst_hi + off, src_h + (c + 1) * 32);
            CP_COMMIT();
        }
        uint32_t bufHiB = swb + (uint32_t)(c & 1) * (5120 * 4) + bOff;
        #pragma unroll
        for (int ks = 0; ks < 2; ++ks) {
            const uint32_t ka4 = (uint32_t)(c * 16 + ks * 8) * 4u;
            uint32_t ah[2][4], bh[2][4];
            ldsm4(ah[0], aHi0 + ka4);
            ldsm4(ah[1], aHi0 + ka4 + aRf);
            ldsm4(bh[0], bufHiB + ks * 32);
            ldsm4(bh[1], bufHiB + ks * 32 + 16 * LDB * 4);
            #pragma unroll
            for (int cf = 0; cf < 4; ++cf) {
                const int p = cf >> 1, ix = (cf & 1) * 2;
                #pragma unroll
                for (int rf = 0; rf < 2; ++rf)
                    MMA_BF16(acc[rf][cf], ah[rf][0], ah[rf][1], ah[rf][2], ah[rf][3],
                             bh[p][ix], bh[p][ix + 1]);
            }
        }
        if (c + 1 < nch) CP_WAIT0();
        __syncthreads();
    }
}

// ================= weight prep: transpose + bf16 split =================
__global__ void prep_kernel(const float* __restrict__ W,
                            __nv_bfloat16* __restrict__ hi,
                            __nv_bfloat16* __restrict__ lo, int Kin, int Kg)
{
    int i = blockIdx.x * blockDim.x + threadIdx.x;
    int tot = LL * 128 * Kg;
    if (i >= tot) return;
    int l = i / (128 * Kg);
    int rem = i - l * 128 * Kg;
    int nn = rem / Kg, k = rem - nn * Kg;
    float v = W[(size_t)l * Kin * 128 + (size_t)k * 128 + nn];
    __nv_bfloat16 h = __float2bfloat16(v);
    hi[i] = h;
    lo[i] = __float2bfloat16(v - __bfloat162float(h));
}

// ================= small utility kernels =================
__global__ void zero2_kernel(float* __restrict__ p1, int n1,
                             float* __restrict__ p2, int n2) {
    int stride = gridDim.x * blockDim.x;
    for (int i = blockIdx.x * blockDim.x + threadIdx.x; i < n1; i += stride)
        p1[i] = 0.f;
    for (int i = blockIdx.x * blockDim.x + threadIdx.x; i < n2; i += stride)
        p2[i] = 0.f;
}
__global__ void zero_kernel(float* __restrict__ p, int n) {
    for (int i = blockIdx.x * blockDim.x + threadIdx.x; i < n; i += gridDim.x * blockDim.x)
        p[i] = 0.f;
}
__global__ void copy_kernel(const float* __restrict__ src, float* __restrict__ dst, int n) {
    int i = blockIdx.x * blockDim.x + threadIdx.x;
    if (i < n) dst[i] = src[i];
}
__global__ void count_kernel(const int* __restrict__ eidx, float* __restrict__ cnt) {
    int e = blockIdx.x * blockDim.x + threadIdx.x;
    if (e < EE) atomicAdd(&cnt[eidx[EE + e]], 1.f);
}

// ================= SMEM layouts =================
#define NX_LO 16896
#define NT_LO 8704
#define NW_B  33792
static const int NODE_SMEM = 44032 * 4;            // 176128 B
static const int PRE_SMEM = 27648 * 4;             // 110592 B
#define ET_LO 8704
#define EW_B  17408
#define E_MISC 27648
static const int EDGE_SMEM = (E_MISC + 1792) * 4;  // 117760 B

// ================= layer-0 node precompute: P1 = h@W1a, P2 = h@W1b =================
__global__ __launch_bounds__(512, 1) void pre_kernel(
    const float* __restrict__ hcur,
    const __nv_bfloat16* __restrict__ W1hi, const __nv_bfloat16* __restrict__ W1lo,
    float* __restrict__ P1, float* __restrict__ P2)
{
    extern __shared__ uint32_t smw[];
    uint32_t* sXhi = smw;
    uint32_t* sXlo = smw + ET_LO;
    uint32_t* sW   = smw + EW_B;

    const int tid = threadIdx.x;
    const int n0 = blockIdx.x * 128;
    const int lane = tid & 31, wid = tid >> 5;
    const int wr = wid & 3, wc = wid >> 2;
    const int g = lane >> 2, t = lane & 3;

    const uint32_t swb = (uint32_t)__cvta_generic_to_shared(sW);
    prestage_w(W1hi, W1lo, 256, swb, tid);

    for (int i = tid; i < 4096; i += 512) {
        int e = i >> 5, q = i & 31;
        int n = n0 + e;
        float4 a = make_float4(0.f, 0.f, 0.f, 0.f);
        if (n < NN) a = *(const float4*)&hcur[(size_t)n * HH + q * 4];
        uint32_t h2, l2, h2b, l2b;
        split2(a.x, a.y, h2, l2); split2(a.z, a.w, h2b, l2b);
        int w = e * LDT + q * 2;
        *(uint2*)&sXhi[w] = make_uint2(h2, h2b);
        *(uint2*)&sXlo[w] = make_uint2(l2, l2b);
    }
    __syncthreads();

    float acc[2][4][4];
    ZERO_ACC(acc);
    wgemm_bf16(W1hi, W1lo, 256, 4, sXhi, sXlo, LDT, sW, tid, acc, 1);
    #pragma unroll
    for (int cf = 0; cf < 4; ++cf) {
        int c0 = wc * 32 + cf * 8 + 2 * t;
        #pragma unroll
        for (int rf = 0; rf < 2; ++rf) {
            int r0 = wr * 32 + rf * 16 + g;
            int na = n0 + r0, nb = n0 + r0 + 8;
            if (na < NN) {
                P1[(size_t)na * HH + c0]     = acc[rf][cf][0];
                P1[(size_t)na * HH + c0 + 1] = acc[rf][cf][1];
            }
            if (nb < NN) {
                P1[(size_t)nb * HH + c0]     = acc[rf][cf][2];
                P1[(size_t)nb * HH + c0 + 1] = acc[rf][cf][3];
            }
        }
    }
    ZERO_ACC(acc);
    wgemm_bf16(W1hi + 128, W1lo + 128, 256, 4, sXhi, sXlo, LDT, sW, tid, acc, 0);
    #pragma unroll
    for (int cf = 0; cf < 4; ++cf) {
        int c0 = wc * 32 + cf * 8 + 2 * t;
        #pragma unroll
        for (int rf = 0; rf < 2; ++rf) {
            int r0 = wr * 32 + rf * 16 + g;
            int na = n0 + r0, nb = n0 + r0 + 8;
            if (na < NN) {
                P2[(size_t)na * HH + c0]     = acc[rf][cf][0];
                P2[(size_t)na * HH + c0 + 1] = acc[rf][cf][1];
            }
            if (nb < NN) {
                P2[(size_t)nb * HH + c0]     = acc[rf][cf][2];
                P2[(size_t)nb * HH + c0 + 1] = acc[rf][cf][3];
            }
        }
    }
}

// ================= fused edge kernel (128 edges/CTA, 512 threads) =================
__global__ __launch_bounds__(512, 1) void edge_kernel(
    const float* __restrict__ P1, const float* __restrict__ P2,
    const float* __restrict__ coords,
    const float* __restrict__ eattr, const int* __restrict__ eidx,
    const __nv_bfloat16* __restrict__ W2hi, const __nv_bfloat16* __restrict__ W2lo,
    const __nv_bfloat16* __restrict__ Wchi, const __nv_bfloat16* __restrict__ Wclo,
    const float* __restrict__ W1tail,
    const float* __restrict__ b1, const float* __restrict__ b2,
    const float* __restrict__ bc1, const float* __restrict__ Wcc,
    float* __restrict__ aggF, float* __restrict__ aggC)
{
    extern __shared__ uint32_t smw[];
    uint32_t* sThi = smw;
    uint32_t* sTlo = smw + ET_LO;
    uint32_t* sW   = smw + EW_B;
    float* sCD   = (float*)(smw + E_MISC);
    float* sDist = sCD + 384;
    float* sEatt = sDist + 128;
    float* sCW   = sEatt + 128;
    int* sIdxC   = (int*)(sCW + 128);
    int* sIdxR   = sIdxC + 128;
    float* sB1   = (float*)(sIdxR + 128);   // 128
    float* sWd   = sB1 + 128;               // 128
    float* sWe   = sWd + 128;               // 128
    float* sB2   = sWe + 128;               // 128
    float* sBC   = sB2 + 128;               // 128
    float* sWc   = sBC + 128;               // 128

    const int tid = threadIdx.x;
    const int lane = tid & 31, wid = tid >> 5;
    const int wr = wid & 3, wc = wid >> 2;
    const int g = lane >> 2, t = lane & 3;

    const uint32_t swb = (uint32_t)__cvta_generic_to_shared(sW);
    prestage_w(W2hi, W2lo, 128, swb, tid);

    if (tid < 128) {
        int e = blockIdx.x * 128 + tid;
        int r = eidx[e], c = eidx[EE + e];
        sIdxR[tid] = r; sIdxC[tid] = c;
        float dx = coords[r * 3 + 0] - coords[c * 3 + 0];
        float dy = coords[r * 3 + 1] - coords[c * 3 + 1];
        float dz = coords[r * 3 + 2] - coords[c * 3 + 2];
        sCD[tid * 3 + 0] = dx; sCD[tid * 3 + 1] = dy; sCD[tid * 3 + 2] = dz;
        sDist[tid] = dx * dx + dy * dy + dz * dz;
        sEatt[tid] = eattr[e];
    } else if (tid < 256) {
        int c = tid - 128;
        sB1[c] = b1[c];
        sWd[c] = W1tail[c];
        sWe[c] = W1tail[128 + c];
    } else if (tid < 384) {
        int c = tid - 256;
        sB2[c] = b2[c];
        sBC[c] = bc1[c];
    } else {
        int c = tid - 384;
        sWc[c] = Wcc[c];
    }
    __syncthreads();

    // stage-1 replacement: t = silu(P1[col] + P2[row] + dist*w256 + ea*w257 + b1)
    for (int i = tid; i < 4096; i += 512) {
        int e = i >> 5, q = i & 31;
        float4 a = *(const float4*)&P1[(size_t)sIdxC[e] * HH + q * 4];
        float4 b = *(const float4*)&P2[(size_t)sIdxR[e] * HH + q * 4];
        float d = sDist[e], ea = sEatt[e];
        int c0 = q * 4;
        float t0 = silu_f(a.x + b.x + d * sWd[c0]     + ea * sWe[c0]     + sB1[c0]);
        float t1 = silu_f(a.y + b.y + d * sWd[c0 + 1] + ea * sWe[c0 + 1] + sB1[c0 + 1]);
        float t2 = silu_f(a.z + b.z + d * sWd[c0 + 2] + ea * sWe[c0 + 2] + sB1[c0 + 2]);
        float t3 = silu_f(a.w + b.w + d * sWd[c0 + 3] + ea * sWe[c0 + 3] + sB1[c0 + 3]);
        uint32_t h2, l2, h2b, l2b;
        split2(t0, t1, h2, l2); split2(t2, t3, h2b, l2b);
        int w = e * LDT + q * 2;
        *(uint2*)&sThi[w] = make_uint2(h2, h2b);
        *(uint2*)&sTlo[w] = make_uint2(l2, l2b);
    }
    __syncthreads();

    float acc[2][4][4];

    // -------- stage 2: ef = silu(t @ W2 + b2); RED aggregate; store ef (hi only) --------
    ZERO_ACC(acc);
    wgemm_bf16(W2hi, W2lo, 128, 4, sThi, sTlo, LDT, sW, tid, acc, 1);
    #pragma unroll
    for (int cf = 0; cf < 4; ++cf) {
        int c0 = wc * 32 + cf * 8 + 2 * t;
        float b2a = sB2[c0], b2b = sB2[c0 + 1];
        #pragma unroll
        for (int rf = 0; rf < 2; ++rf) {
            int r0 = wr * 32 + rf * 16 + g;
            float v00 = silu_f(acc[rf][cf][0] + b2a);
            float v01 = silu_f(acc[rf][cf][1] + b2b);
            float v10 = silu_f(acc[rf][cf][2] + b2a);
            float v11 = silu_f(acc[rf][cf][3] + b2b);
            red2(&aggF[(size_t)sIdxC[r0] * HH + c0], v00, v01);
            red2(&aggF[(size_t)sIdxC[r0 + 8] * HH + c0], v10, v11);
            int w0 = r0 * LDT + wc * 16 + cf * 4 + t;
            sThi[w0] = bf16pack(v00, v01);
            sThi[w0 + 8 * LDT] = bf16pack(v10, v11);
        }
    }
    __syncthreads();

    // -------- stage 3 (pure bf16): cw = silu(ef @ Wc1 + bc1) @ Wcc --------
    ZERO_ACC(acc);
    wgemm_bf16_1t(Wchi, 128, 4, sThi, LDT, sW, tid, acc);
    if (tid < 128) sCW[tid] = 0.f;
    __syncthreads();
    #pragma unroll
    for (int rf = 0; rf < 2; ++rf) {
        float pa = 0.f, pb = 0.f;
        #pragma unroll
        for (int cf = 0; cf < 4; ++cf) {
            int c0 = wc * 32 + cf * 8 + 2 * t;
            float ba = sBC[c0], bb = sBC[c0 + 1];
            float wa = sWc[c0], wb = sWc[c0 + 1];
            pa = fmaf(silu_f(acc[rf][cf][0] + ba), wa, pa);
            pa = fmaf(silu_f(acc[rf][cf][1] + bb), wb, pa);
            pb = fmaf(silu_f(acc[rf][cf][2] + ba), wa, pb);
            pb = fmaf(silu_f(acc[rf][cf][3] + bb), wb, pb);
        }
        pa += __shfl_xor_sync(0xffffffffu, pa, 1);
        pa += __shfl_xor_sync(0xffffffffu, pa, 2);
        pb += __shfl_xor_sync(0xffffffffu, pb, 1);
        pb += __shfl_xor_sync(0xffffffffu, pb, 2);
        if (t == 0) {
            int r0 = wr * 32 + rf * 16 + g;
            atomicAdd(&sCW[r0], pa);
            atomicAdd(&sCW[r0 + 8], pb);
        }
    }
    __syncthreads();
    if (tid < 128) {
        float cw = sCW[tid];
        int cn = sIdxC[tid];
        atomicAdd(&aggC[cn * 3 + 0], sCD[tid * 3 + 0] * cw);
        atomicAdd(&aggC[cn * 3 + 1], sCD[tid * 3 + 1] * cw);
        atomicAdd(&aggC[cn * 3 + 2], sCD[tid * 3 + 2] * cw);
    }
}

// ================= node update + fused next-layer precompute + agg re-zero =================
__global__ __launch_bounds__(512, 1) void node_kernel(
    float* __restrict__ h, float* __restrict__ coords,
    float* __restrict__ aggF, float* __restrict__ aggC,
    const float* __restrict__ cnt,
    const __nv_bfloat16* __restrict__ W1hi, const __nv_bfloat16* __restrict__ W1lo,
    const __nv_bfloat16* __restrict__ W2hi, const __nv_bfloat16* __restrict__ W2lo,
    const float* __restrict__ b1, const float* __restrict__ b2,
    const __nv_bfloat16* __restrict__ nx1hi, const __nv_bfloat16* __restrict__ nx1lo,
    float* __restrict__ P1, float* __restrict__ P2, int do_pre)
{
    extern __shared__ uint32_t smw[];
    uint32_t* sXhi = smw;
    uint32_t* sXlo = smw + NX_LO;
    uint32_t* sThi = smw;
    uint32_t* sTlo = smw + NT_LO;
    uint32_t* sW   = smw + NW_B;

    const int tid = threadIdx.x;
    const int n0 = blockIdx.x * 128;
    const int lane = tid & 31, wid = tid >> 5;
    const int wr = wid & 3, wc = wid >> 2;
    const int g = lane >> 2, t = lane & 3;

    const uint32_t swb = (uint32_t)__cvta_generic_to_shared(sW);
    prestage_w(W1hi, W1lo, 256, swb, tid);

    for (int i = tid; i < 4096; i += 512) {
        int e = i >> 5, q = i & 31;
        int n = n0 + e;
        float4 a = make_float4(0.f, 0.f, 0.f, 0.f), b = a;
        if (n < NN) {
            a = *(const float4*)&h[(size_t)n * HH + q * 4];
            b = *(const float4*)&aggF[(size_t)n * HH + q * 4];
            // re-zero aggF for next layer's edge pass (fused zeroing)
            *(float4*)&aggF[(size_t)n * HH + q * 4] = make_float4(0.f, 0.f, 0.f, 0.f);
        }
        uint32_t h2, l2, h2b, l2b;
        split2(a.x, a.y, h2, l2); split2(a.z, a.w, h2b, l2b);
        int w = e * LDX + q * 2;
        *(uint2*)&sXhi[w] = make_uint2(h2, h2b);
        *(uint2*)&sXlo[w] = make_uint2(l2, l2b);
        split2(b.x, b.y, h2, l2); split2(b.z, b.w, h2b, l2b);
        *(uint2*)&sXhi[w + 64] = make_uint2(h2, h2b);
        *(uint2*)&sXlo[w + 64] = make_uint2(l2, l2b);
    }
    __syncthreads();

    float acc[2][4][4];
    ZERO_ACC(acc);
    wgemm_bf16(W1hi, W1lo, 256, 8, sXhi, sXlo, LDX, sW, tid, acc, 1);
    #pragma unroll
    for (int cf = 0; cf < 4; ++cf) {
        int c0 = wc * 32 + cf * 8 + 2 * t;
        float b1a = __ldg(&b1[c0]), b1b = __ldg(&b1[c0 + 1]);
        #pragma unroll
        for (int rf = 0; rf < 2; ++rf) {
            int r0 = wr * 32 + rf * 16 + g;
            float t00 = silu_f(acc[rf][cf][0] + b1a);
            float t01 = silu_f(acc[rf][cf][1] + b1b);
            float t10 = silu_f(acc[rf][cf][2] + b1a);
            float t11 = silu_f(acc[rf][cf][3] + b1b);
            uint32_t h2, l2;
            int w0 = r0 * LDT + wc * 16 + cf * 4 + t;
            split2(t00, t01, h2, l2); sThi[w0] = h2; sTlo[w0] = l2;
            split2(t10, t11, h2, l2); sThi[w0 + 8 * LDT] = h2; sTlo[w0 + 8 * LDT] = l2;
        }
    }
    __syncthreads();

    ZERO_ACC(acc);
    wgemm_bf16(W2hi, W2lo, 128, 4, sThi, sTlo, LDT, sW, tid, acc, 0);
    #pragma unroll
    for (int cf = 0; cf < 4; ++cf) {
        int c0 = wc * 32 + cf * 8 + 2 * t;
        float b2a = __ldg(&b2[c0]), b2b = __ldg(&b2[c0 + 1]);
        #pragma unroll
        for (int rf = 0; rf < 2; ++rf) {
            int r0 = wr * 32 + rf * 16 + g;
            int na = n0 + r0, nb = n0 + r0 + 8;
            float v00 = 0.f, v01 = 0.f, v10 = 0.f, v11 = 0.f;
            if (na < NN) {
                size_t idx = (size_t)na * HH + c0;
                v00 = h[idx] + acc[rf][cf][0] + b2a;
                v01 = h[idx + 1] + acc[rf][cf][1] + b2b;
                h[idx] = v00; h[idx + 1] = v01;
            }
            if (nb < NN) {
                size_t idx = (size_t)nb * HH + c0;
                v10 = h[idx] + acc[rf][cf][2] + b2a;
                v11 = h[idx + 1] + acc[rf][cf][3] + b2b;
                h[idx] = v10; h[idx + 1] = v11;
            }
            if (do_pre) {
                uint32_t h2, l2;
                int w0 = r0 * LDT + wc * 16 + cf * 4 + t;
                split2(v00, v01, h2, l2); sThi[w0] = h2; sTlo[w0] = l2;
                split2(v10, v11, h2, l2); sThi[w0 + 8 * LDT] = h2; sTlo[w0 + 8 * LDT] = l2;
            }
        }
    }

    if (tid < 384) {
        int n = n0 + tid / 3, d = tid % 3;
        if (n < NN) {
            float cv = cnt[n];
            cv = cv < 1.f ? 1.f : cv;
            coords[n * 3 + d] += aggC[n * 3 + d] / cv;
            aggC[n * 3 + d] = 0.f;   // re-zero for next layer
        }
    }

    if (do_pre) {
        __syncthreads();
        ZERO_ACC(acc);
        wgemm_bf16(nx1hi, nx1lo, 256, 4, sThi, sTlo, LDT, sW, tid, acc, 0);
        #pragma unroll
        for (int cf = 0; cf < 4; ++cf) {
            int c0 = wc * 32 + cf * 8 + 2 * t;
            #pragma unroll
            for (int rf = 0; rf < 2; ++rf) {
                int r0 = wr * 32 + rf * 16 + g;
                int na = n0 + r0, nb = n0 + r0 + 8;
                if (na < NN) {
                    P1[(size_t)na * HH + c0]     = acc[rf][cf][0];
                    P1[(size_t)na * HH + c0 + 1] = acc[rf][cf][1];
                }
                if (nb < NN) {
                    P1[(size_t)nb * HH + c0]     = acc[rf][cf][2];
                    P1[(size_t)nb * HH + c0 + 1] = acc[rf][cf][3];
                }
            }
        }
        ZERO_ACC(acc);
        wgemm_bf16(nx1hi + 128, nx1lo + 128, 256, 4, sThi, sTlo, LDT, sW, tid, acc, 0);
        #pragma unroll
        for (int cf = 0; cf < 4; ++cf) {
            int c0 = wc * 32 + cf * 8 + 2 * t;
            #pragma unroll
            for (int rf = 0; rf < 2; ++rf) {
                int r0 = wr * 32 + rf * 16 + g;
                int na = n0 + r0, nb = n0 + r0 + 8;
                if (na < NN) {
                    P2[(size_t)na * HH + c0]     = acc[rf][cf][0];
                    P2[(size_t)na * HH + c0 + 1] = acc[rf][cf][1];
                }
                if (nb < NN) {
                    P2[(size_t)nb * HH + c0]     = acc[rf][cf][2];
                    P2[(size_t)nb * HH + c0 + 1] = acc[rf][cf][3];
                }
            }
        }
    }
}

// ================= FFMA linear (small embeddings only) =================
__device__ __forceinline__ void bgemm(const float* __restrict__ gW,
                                      const float* sIn, int ldi,
                                      float* sW, int K, int tid,
                                      float acc[4][8])
{
    const int nI = tid & 15;
    const int eI = tid >> 4;
    for (int k0 = 0; k0 < K; k0 += 32) {
        const int kc = (K - k0) < 32 ? (K - k0) : 32;
        for (int i = tid; i < (kc << 5); i += 256) {
            int r = i >> 5, q = i & 31;
            *(float4*)&sW[r * 128 + q * 4] =
                *(const float4*)&gW[(size_t)(k0 + r) * 128 + q * 4];
        }
        __syncthreads();
        const float* x0p = sIn + (eI * 4 + 0) * ldi + k0;
        const float* x1p = sIn + (eI * 4 + 1) * ldi + k0;
        const float* x2p = sIn + (eI * 4 + 2) * ldi + k0;
        const float* x3p = sIn + (eI * 4 + 3) * ldi + k0;
        for (int r = 0; r < kc; ++r) {
            float xv[4] = {x0p[r], x1p[r], x2p[r], x3p[r]};
            float4 wa = *(const float4*)&sW[r * 128 + nI * 8];
            float4 wb = *(const float4*)&sW[r * 128 + nI * 8 + 4];
            float wv[8] = {wa.x, wa.y, wa.z, wa.w, wb.x, wb.y, wb.z, wb.w};
            #pragma unroll
            for (int a = 0; a < 4; ++a)
                #pragma unroll
                for (int c = 0; c < 8; ++c)
                    acc[a][c] = fmaf(xv[a], wv[c], acc[a][c]);
        }
        __syncthreads();
    }
}

static const int LIN_SMEM = (64 * 260 + 32 * 128) * 4;

__global__ __launch_bounds__(256, 1) void linear_kernel(
    const float* __restrict__ Xg, int K,
    const float* __restrict__ W, const float* __restrict__ b,
    float* __restrict__ Y, int nrows)
{
    extern __shared__ float smf[];
    float* sX = smf;
    float* sW = sX + 64 * 260;
    int tid = threadIdx.x;
    int n0 = blockIdx.x * 64;
    int kq = K >> 2;
    for (int i = tid; i < 64 * kq; i += 256) {
        int e = i / kq, q = i % kq;
        int n = n0 + e;
        float4 v = make_float4(0.f, 0.f, 0.f, 0.f);
        if (n < nrows) v = *(const float4*)&Xg[(size_t)n * K + q * 4];
        *(float4*)&sX[e * 260 + q * 4] = v;
    }
    __syncthreads();
    float acc[4][8];
    #pragma unroll
    for (int a = 0; a < 4; ++a)
        #pragma unroll
        for (int c = 0; c < 8; ++c) acc[a][c] = 0.f;
    bgemm(W, sX, 260, sW, K, tid, acc);
    int nI = tid & 15, eI = tid >> 4;
    float bias[8];
    #pragma unroll
    for (int c = 0; c < 8; ++c) bias[c] = __ldg(&b[nI * 8 + c]);
    #pragma unroll
    for (int a = 0; a < 4; ++a) {
        int n = n0 + eI * 4 + a;
        if (n < nrows) {
            #pragma unroll
            for (int c = 0; c < 8; ++c)
                Y[(size_t)n * 128 + nI * 8 + c] = acc[a][c] + bias[c];
        }
    }
}

// ================= host launcher =================
extern "C" void kernel_launch(void* const* d_in, const int* in_sizes, int n_in,
                              void* d_out, int out_size)
{
    (void)in_sizes; (void)n_in; (void)out_size;
    const float* h_in   = (const float*)d_in[0];
    const float* coords = (const float*)d_in[1];
    const float* eattr  = (const float*)d_in[2];
    const float* embiW  = (const float*)d_in[3];
    const float* embib  = (const float*)d_in[4];
    const float* emboW  = (const float*)d_in[5];
    const float* embob  = (const float*)d_in[6];
    const float* eW1    = (const float*)d_in[7];
    const float* eb1    = (const float*)d_in[8];
    const float* eW2    = (const float*)d_in[9];
    const float* eb2    = (const float*)d_in[10];
    const float* cW1    = (const float*)d_in[11];
    const float* cb1    = (const float*)d_in[12];
    const float* cWc    = (const float*)d_in[13];
    const float* nW1    = (const float*)d_in[14];
    const float* nb1    = (const float*)d_in[15];
    const float* nW2    = (const float*)d_in[16];
    const float* nb2    = (const float*)d_in[17];
    const int*   eidx   = (const int*)d_in[18];
    float* out = (float*)d_out;

    cudaFuncSetAttribute(edge_kernel,   cudaFuncAttributeMaxDynamicSharedMemorySize, EDGE_SMEM);
    cudaFuncSetAttribute(node_kernel,   cudaFuncAttributeMaxDynamicSharedMemorySize, NODE_SMEM);
    cudaFuncSetAttribute(pre_kernel,    cudaFuncAttributeMaxDynamicSharedMemorySize, PRE_SMEM);
    cudaFuncSetAttribute(linear_kernel, cudaFuncAttributeMaxDynamicSharedMemorySize, LIN_SMEM);

    float *p_h, *p_coords, *p_aggF, *p_aggC, *p_cnt, *p_P1, *p_P2;
    cudaGetSymbolAddress((void**)&p_h, g_h);
    cudaGetSymbolAddress((void**)&p_coords, g_coords);
    cudaGetSymbolAddress((void**)&p_aggF, g_aggF);
    cudaGetSymbolAddress((void**)&p_aggC, g_aggC);
    cudaGetSymbolAddress((void**)&p_cnt, g_cnt);
    cudaGetSymbolAddress((void**)&p_P1, g_P1);
    cudaGetSymbolAddress((void**)&p_P2, g_P2);

    __nv_bfloat16 *pe1h, *pe1l, *pe2h, *pe2l, *pch, *pcl, *pn1h, *pn1l, *pn2h, *pn2l;
    cudaGetSymbolAddress((void**)&pe1h, g_eW1hi); cudaGetSymbolAddress((void**)&pe1l, g_eW1lo);
    cudaGetSymbolAddress((void**)&pe2h, g_eW2hi); cudaGetSymbolAddress((void**)&pe2l, g_eW2lo);
    cudaGetSymbolAddress((void**)&pch,  g_cW1hi); cudaGetSymbolAddress((void**)&pcl,  g_cW1lo);
    cudaGetSymbolAddress((void**)&pn1h, g_nW1hi); cudaGetSymbolAddress((void**)&pn1l, g_nW1lo);
    cudaGetSymbolAddress((void**)&pn2h, g_nW2hi); cudaGetSymbolAddress((void**)&pn2l, g_nW2lo);

    const int NB_N = (NN + 127) / 128;   // 391
    const int NB_E = EE / 128;           // 6250
    const int NB_L = (NN + 63) / 64;     // 782

    prep_kernel<<<LL * 128, 256>>>(eW1, pe1h, pe1l, K1, 256);
    prep_kernel<<<LL * 64, 256>>>(eW2, pe2h, pe2l, HH, 128);
    prep_kernel<<<LL * 64, 256>>>(cW1, pch, pcl, HH, 128);
    prep_kernel<<<LL * 128, 256>>>(nW1, pn1h, pn1l, 2 * HH, 256);
    prep_kernel<<<LL * 64, 256>>>(nW2, pn2h, pn2l, HH, 128);

    zero_kernel<<<256, 256>>>(p_cnt, NN);
    count_kernel<<<(EE + 255) / 256, 256>>>(eidx, p_cnt);

    linear_kernel<<<NB_L, 256, LIN_SMEM>>>(h_in, INCH, embiW, embib, p_h, NN);
    copy_kernel<<<(NN * 3 + 255) / 256, 256>>>(coords, p_coords, NN * 3);

    pre_kernel<<<NB_N, 512, PRE_SMEM>>>(p_h, pe1h, pe1l, p_P1, p_P2);

    // initial zero of agg buffers (subsequent layers re-zeroed inside node_kernel)
    zero2_kernel<<<512, 256>>>(p_aggF, NN * HH, p_aggC, NN * 3);

    for (int l = 0; l < LL; ++l) {
        edge_kernel<<<NB_E, 512, EDGE_SMEM>>>(
            p_P1, p_P2, p_coords, eattr, eidx,
            pe2h + (size_t)l * 128 * 128, pe2l + (size_t)l * 128 * 128,
            pch  + (size_t)l * 128 * 128, pcl  + (size_t)l * 128 * 128,
            eW1 + (size_t)l * K1 * HH + 256 * HH,
            eb1 + (size_t)l * HH, eb2 + (size_t)l * HH,
            cb1 + (size_t)l * HH, cWc + (size_t)l * HH,
            p_aggF, p_aggC);
        int do_pre = (l + 1 < LL) ? 1 : 0;
        const __nv_bfloat16* nx1h = pe1h + (size_t)(do_pre ? l + 1 : l) * 128 * 256;
        const __nv_bfloat16* nx1l = pe1l + (size_t)(do_pre ? l + 1 : l) * 128 * 256;
        node_kernel<<<NB_N, 512, NODE_SMEM>>>(
            p_h, p_coords, p_aggF, p_aggC, p_cnt,
            pn1h + (size_t)l * 128 * 256, pn1l + (size_t)l * 128 * 256,
            pn2h + (size_t)l * 128 * 128, pn2l + (size_t)l * 128 * 128,
            nb1 + (size_t)l * HH, nb2 + (size_t)l * HH,
            nx1h, nx1l, p_P1, p_P2, do_pre);
    }

    linear_kernel<<<NB_L, 256, LIN_SMEM>>>(p_h, HH, emboW, embob, out, NN);
    copy_kernel<<<(NN * 3 + 255) / 256, 256>>>(p_coords, out + (size_t)NN * HH, NN * 3);
}

// round 16
// speedup vs baseline: 1.0971x; 1.0971x over previous
#include <cuda_runtime.h>
#include <cuda_bf16.h>
#include <cstdint>

#define NN 50000
#define EE 800000
#define HH 128
#define INCH 64
#define LL 4
#define K1 258

// word strides (uint32 units)
#define LDX 132   // node sX: 264 bf16/row
#define LDT 68    // sT / pre sX: 136 bf16/row
#define LDB 20    // sW: 40 bf16/row

// ================= scratch (__device__ globals; no allocation) =================
__device__ float g_h[(size_t)NN * HH];
__device__ float g_coords[(size_t)NN * 3];
__device__ float g_aggF[(size_t)NN * HH];
__device__ float g_aggC[(size_t)NN * 3];
__device__ float g_cnt[NN];
__device__ float g_P1[(size_t)NN * HH];
__device__ float g_P2[(size_t)NN * HH];
// pre-transposed + bf16-split weights: [L][n=128][k]
__device__ __align__(16) __nv_bfloat16 g_eW1hi[(size_t)LL * 128 * 256];
__device__ __align__(16) __nv_bfloat16 g_eW1lo[(size_t)LL * 128 * 256];
__device__ __align__(16) __nv_bfloat16 g_eW2hi[(size_t)LL * 128 * 128];
__device__ __align__(16) __nv_bfloat16 g_eW2lo[(size_t)LL * 128 * 128];
__device__ __align__(16) __nv_bfloat16 g_cW1hi[(size_t)LL * 128 * 128];
__device__ __align__(16) __nv_bfloat16 g_cW1lo[(size_t)LL * 128 * 128];
__device__ __align__(16) __nv_bfloat16 g_nW1hi[(size_t)LL * 128 * 256];
__device__ __align__(16) __nv_bfloat16 g_nW1lo[(size_t)LL * 128 * 256];
__device__ __align__(16) __nv_bfloat16 g_nW2hi[(size_t)LL * 128 * 128];
__device__ __align__(16) __nv_bfloat16 g_nW2lo[(size_t)LL * 128 * 128];

__device__ __forceinline__ float silu_f(float x) {
    return x * __fdividef(1.f, 1.f + __expf(-x));
}

__device__ __forceinline__ uint32_t bf16pack(float f0, float f1) {
    uint32_t d;
    asm("cvt.rn.bf16x2.f32 %0, %1, %2;" : "=r"(d) : "f"(f1), "f"(f0));
    return d;
}
__device__ __forceinline__ void split2(float f0, float f1, uint32_t& h2, uint32_t& l2) {
    h2 = bf16pack(f0, f1);
    float h0 = __uint_as_float(h2 << 16);
    float h1 = __uint_as_float(h2 & 0xffff0000u);
    l2 = bf16pack(f0 - h0, f1 - h1);
}

__device__ __forceinline__ void cp_async16(uint32_t dst, const void* src) {
    asm volatile("cp.async.ca.shared.global [%0], [%1], 16;" :: "r"(dst), "l"(src));
}
#define CP_COMMIT() asm volatile("cp.async.commit_group;" ::: "memory")
#define CP_WAIT0()  asm volatile("cp.async.wait_group 0;" ::: "memory")

__device__ __forceinline__ void ldsm4(uint32_t* r, uint32_t addr) {
    asm volatile("ldmatrix.sync.aligned.m8n8.x4.shared.b16 {%0,%1,%2,%3}, [%4];"
                 : "=r"(r[0]), "=r"(r[1]), "=r"(r[2]), "=r"(r[3]) : "r"(addr));
}

__device__ __forceinline__ void red2(float* p, float a, float b) {
    asm volatile("red.global.add.v2.f32 [%0], {%1,%2};" :: "l"(p), "f"(a), "f"(b) : "memory");
}

#define MMA_BF16(d, a0, a1, a2, a3, b0, b1) \
    asm volatile("mma.sync.aligned.m16n8k16.row.col.f32.bf16.bf16.f32 " \
                 "{%0,%1,%2,%3}, {%4,%5,%6,%7}, {%8,%9}, {%0,%1,%2,%3};" \
                 : "+f"((d)[0]), "+f"((d)[1]), "+f"((d)[2]), "+f"((d)[3]) \
                 : "r"(a0), "r"(a1), "r"(a2), "r"(a3), "r"(b0), "r"(b1))

#define ZERO_ACC(acc) do { \
    _Pragma("unroll") for (int _r = 0; _r < 2; ++_r) \
    _Pragma("unroll") for (int _c = 0; _c < 4; ++_c) \
    _Pragma("unroll") for (int _q = 0; _q < 4; ++_q) acc[_r][_c][_q] = 0.f; } while (0)

// =================== bf16x3 warp-tiled GEMM (128 x 128, 16 warps, ldmatrix) ===================
__device__ __forceinline__ void wgemm_bf16(
    const __nv_bfloat16* __restrict__ gHi, const __nv_bfloat16* __restrict__ gLo,
    int Kg, int nch,
    const uint32_t* sInHi, const uint32_t* sInLo, int ldw,
    uint32_t* sW, int tid, float acc[2][4][4])
{
    const int lane = tid & 31, wid = tid >> 5;
    const int wr = wid & 3, wc = wid >> 2;
    const int n = tid >> 2, seg = tid & 3;

    uint32_t swb = (uint32_t)__cvta_generic_to_shared(sW);
    uint32_t dst_hi = swb + (n * LDB + seg * 4) * 4;
    uint32_t dst_lo = dst_hi + 2560 * 4;
    const __nv_bfloat16* src_h = gHi + (size_t)n * Kg + seg * 8;
    const __nv_bfloat16* src_l = gLo + (size_t)n * Kg + seg * 8;

    cp_async16(dst_hi, src_h);
    cp_async16(dst_lo, src_l);
    CP_COMMIT(); CP_WAIT0();
    __syncthreads();

    const uint32_t aOff = (uint32_t)(wr * 32 + (lane & 15)) * (uint32_t)ldw * 4u
                        + (uint32_t)(lane >> 4) * 16u;
    const uint32_t aHi0 = (uint32_t)__cvta_generic_to_shared(sInHi) + aOff;
    const uint32_t aLo0 = (uint32_t)__cvta_generic_to_shared(sInLo) + aOff;
    const uint32_t aRf = (uint32_t)(16 * ldw * 4);
    const uint32_t bOff = (uint32_t)(wc * 32 + ((lane >> 4) << 3) + (lane & 7)) * (LDB * 4u)
                        + (uint32_t)((lane >> 3) & 1) * 16u;

    for (int c = 0; c < nch; ++c) {
        if (c + 1 < nch) {
            uint32_t off = (uint32_t)((c + 1) & 1) * (5120 * 4);
            cp_async16(dst_hi + off, src_h + (c + 1) * 32);
            cp_async16(dst_lo + off, src_l + (c + 1) * 32);
            CP_COMMIT();
        }
        uint32_t bufHiB = swb + (uint32_t)(c & 1) * (5120 * 4) + bOff;
        uint32_t bufLoB = bufHiB + 2560 * 4;
        #pragma unroll
        for (int ks = 0; ks < 2; ++ks) {
            const uint32_t ka4 = (uint32_t)(c * 16 + ks * 8) * 4u;
            uint32_t ah[2][4], al[2][4], bh[2][4], bl[2][4];
            ldsm4(ah[0], aHi0 + ka4);
            ldsm4(ah[1], aHi0 + ka4 + aRf);
            ldsm4(al[0], aLo0 + ka4);
            ldsm4(al[1], aLo0 + ka4 + aRf);
            ldsm4(bh[0], bufHiB + ks * 32);
            ldsm4(bh[1], bufHiB + ks * 32 + 16 * LDB * 4);
            ldsm4(bl[0], bufLoB + ks * 32);
            ldsm4(bl[1], bufLoB + ks * 32 + 16 * LDB * 4);
            #pragma unroll
            for (int cf = 0; cf < 4; ++cf) {
                const int p = cf >> 1, ix = (cf & 1) * 2;
                #pragma unroll
                for (int rf = 0; rf < 2; ++rf)
                    MMA_BF16(acc[rf][cf], ah[rf][0], ah[rf][1], ah[rf][2], ah[rf][3],
                             bl[p][ix], bl[p][ix + 1]);
            }
            #pragma unroll
            for (int cf = 0; cf < 4; ++cf) {
                const int p = cf >> 1, ix = (cf & 1) * 2;
                #pragma unroll
                for (int rf = 0; rf < 2; ++rf)
                    MMA_BF16(acc[rf][cf], al[rf][0], al[rf][1], al[rf][2], al[rf][3],
                             bh[p][ix], bh[p][ix + 1]);
            }
            #pragma unroll
            for (int cf = 0; cf < 4; ++cf) {
                const int p = cf >> 1, ix = (cf & 1) * 2;
                #pragma unroll
                for (int rf = 0; rf < 2; ++rf)
                    MMA_BF16(acc[rf][cf], ah[rf][0], ah[rf][1], ah[rf][2], ah[rf][3],
                             bh[p][ix], bh[p][ix + 1]);
            }
        }
        if (c + 1 < nch) CP_WAIT0();
        __syncthreads();
    }
}

// pure-bf16 single-term variant: A hi only, B hi only. D += Ah*Bh.
__device__ __forceinline__ void wgemm_bf16_1t(
    const __nv_bfloat16* __restrict__ gHi,
    int Kg, int nch,
    const uint32_t* sInHi, int ldw,
    uint32_t* sW, int tid, float acc[2][4][4])
{
    const int lane = tid & 31, wid = tid >> 5;
    const int wr = wid & 3, wc = wid >> 2;
    const int n = tid >> 2, seg = tid & 3;

    uint32_t swb = (uint32_t)__cvta_generic_to_shared(sW);
    uint32_t dst_hi = swb + (n * LDB + seg * 4) * 4;
    const __nv_bfloat16* src_h = gHi + (size_t)n * Kg + seg * 8;

    cp_async16(dst_hi, src_h);
    CP_COMMIT(); CP_WAIT0();
    __syncthreads();

    const uint32_t aOff = (uint32_t)(wr * 32 + (lane & 15)) * (uint32_t)ldw * 4u
                        + (uint32_t)(lane >> 4) * 16u;
    const uint32_t aHi0 = (uint32_t)__cvta_generic_to_shared(sInHi) + aOff;
    const uint32_t aRf = (uint32_t)(16 * ldw * 4);
    const uint32_t bOff = (uint32_t)(wc * 32 + ((lane >> 4) << 3) + (lane & 7)) * (LDB * 4u)
                        + (uint32_t)((lane >> 3) & 1) * 16u;

    for (int c = 0; c < nch; ++c) {
        if (c + 1 < nch) {
            uint32_t off = (uint32_t)((c + 1) & 1) * (5120 * 4);
            cp_async16(dst_hi + off, src_h + (c + 1) * 32);
            CP_COMMIT();
        }
        uint32_t bufHiB = swb + (uint32_t)(c & 1) * (5120 * 4) + bOff;
        #pragma unroll
        for (int ks = 0; ks < 2; ++ks) {
            const uint32_t ka4 = (uint32_t)(c * 16 + ks * 8) * 4u;
            uint32_t ah[2][4], bh[2][4];
            ldsm4(ah[0], aHi0 + ka4);
            ldsm4(ah[1], aHi0 + ka4 + aRf);
            ldsm4(bh[0], bufHiB + ks * 32);
            ldsm4(bh[1], bufHiB + ks * 32 + 16 * LDB * 4);
            #pragma unroll
            for (int cf = 0; cf < 4; ++cf) {
                const int p = cf >> 1, ix = (cf & 1) * 2;
                #pragma unroll
                for (int rf = 0; rf < 2; ++rf)
                    MMA_BF16(acc[rf][cf], ah[rf][0], ah[rf][1], ah[rf][2], ah[rf][3],
                             bh[p][ix], bh[p][ix + 1]);
            }
        }
        if (c + 1 < nch) CP_WAIT0();
        __syncthreads();
    }
}

// ================= weight prep: transpose + bf16 split =================
__global__ void prep_kernel(const float* __restrict__ W,
                            __nv_bfloat16* __restrict__ hi,
                            __nv_bfloat16* __restrict__ lo, int Kin, int Kg)
{
    int i = blockIdx.x * blockDim.x + threadIdx.x;
    int tot = LL * 128 * Kg;
    if (i >= tot) return;
    int l = i / (128 * Kg);
    int rem = i - l * 128 * Kg;
    int nn = rem / Kg, k = rem - nn * Kg;
    float v = W[(size_t)l * Kin * 128 + (size_t)k * 128 + nn];
    __nv_bfloat16 h = __float2bfloat16(v);
    hi[i] = h;
    lo[i] = __float2bfloat16(v - __bfloat162float(h));
}

// ================= small utility kernels =================
__global__ void zero_kernel(float* __restrict__ p, int n) {
    for (int i = blockIdx.x * blockDim.x + threadIdx.x; i < n; i += gridDim.x * blockDim.x)
        p[i] = 0.f;
}
__global__ void copy_kernel(const float* __restrict__ src, float* __restrict__ dst, int n) {
    int i = blockIdx.x * blockDim.x + threadIdx.x;
    if (i < n) dst[i] = src[i];
}
__global__ void count_kernel(const int* __restrict__ eidx, float* __restrict__ cnt) {
    int e = blockIdx.x * blockDim.x + threadIdx.x;
    if (e < EE) atomicAdd(&cnt[eidx[EE + e]], 1.f);
}

// ================= SMEM layouts =================
#define NX_LO 16896
#define NT_LO 8704
#define NW_B  33792
static const int NODE_SMEM = 44032 * 4;            // 176128 B
static const int PRE_SMEM = 27648 * 4;             // 110592 B
#define ET_LO 8704
#define EW_B  17408
#define E_MISC 27648
static const int EDGE_SMEM = (E_MISC + 1408) * 4;  // 116224 B

// ================= layer-0 node precompute: P1 = h@W1a, P2 = h@W1b =================
__global__ __launch_bounds__(512, 1) void pre_kernel(
    const float* __restrict__ hcur,
    const __nv_bfloat16* __restrict__ W1hi, const __nv_bfloat16* __restrict__ W1lo,
    float* __restrict__ P1, float* __restrict__ P2)
{
    extern __shared__ uint32_t smw[];
    uint32_t* sXhi = smw;
    uint32_t* sXlo = smw + ET_LO;
    uint32_t* sW   = smw + EW_B;

    const int tid = threadIdx.x;
    const int n0 = blockIdx.x * 128;
    const int lane = tid & 31, wid = tid >> 5;
    const int wr = wid & 3, wc = wid >> 2;
    const int g = lane >> 2, t = lane & 3;

    for (int i = tid; i < 4096; i += 512) {
        int e = i >> 5, q = i & 31;
        int n = n0 + e;
        float4 a = make_float4(0.f, 0.f, 0.f, 0.f);
        if (n < NN) a = *(const float4*)&hcur[(size_t)n * HH + q * 4];
        uint32_t h2, l2, h2b, l2b;
        split2(a.x, a.y, h2, l2); split2(a.z, a.w, h2b, l2b);
        int w = e * LDT + q * 2;
        *(uint2*)&sXhi[w] = make_uint2(h2, h2b);
        *(uint2*)&sXlo[w] = make_uint2(l2, l2b);
    }
    __syncthreads();

    float acc[2][4][4];
    ZERO_ACC(acc);
    wgemm_bf16(W1hi, W1lo, 256, 4, sXhi, sXlo, LDT, sW, tid, acc);
    #pragma unroll
    for (int cf = 0; cf < 4; ++cf) {
        int c0 = wc * 32 + cf * 8 + 2 * t;
        #pragma unroll
        for (int rf = 0; rf < 2; ++rf) {
            int r0 = wr * 32 + rf * 16 + g;
            int na = n0 + r0, nb = n0 + r0 + 8;
            if (na < NN) {
                P1[(size_t)na * HH + c0]     = acc[rf][cf][0];
                P1[(size_t)na * HH + c0 + 1] = acc[rf][cf][1];
            }
            if (nb < NN) {
                P1[(size_t)nb * HH + c0]     = acc[rf][cf][2];
                P1[(size_t)nb * HH + c0 + 1] = acc[rf][cf][3];
            }
        }
    }
    ZERO_ACC(acc);
    wgemm_bf16(W1hi + 128, W1lo + 128, 256, 4, sXhi, sXlo, LDT, sW, tid, acc);
    #pragma unroll
    for (int cf = 0; cf < 4; ++cf) {
        int c0 = wc * 32 + cf * 8 + 2 * t;
        #pragma unroll
        for (int rf = 0; rf < 2; ++rf) {
            int r0 = wr * 32 + rf * 16 + g;
            int na = n0 + r0, nb = n0 + r0 + 8;
            if (na < NN) {
                P2[(size_t)na * HH + c0]     = acc[rf][cf][0];
                P2[(size_t)na * HH + c0 + 1] = acc[rf][cf][1];
            }
            if (nb < NN) {
                P2[(size_t)nb * HH + c0]     = acc[rf][cf][2];
                P2[(size_t)nb * HH + c0 + 1] = acc[rf][cf][3];
            }
        }
    }
}

// ================= fused edge kernel (128 edges/CTA, 512 threads) =================
__global__ __launch_bounds__(512, 1) void edge_kernel(
    const float* __restrict__ P1, const float* __restrict__ P2,
    const float* __restrict__ coords,
    const float* __restrict__ eattr, const int* __restrict__ eidx,
    const __nv_bfloat16* __restrict__ W2hi, const __nv_bfloat16* __restrict__ W2lo,
    const __nv_bfloat16* __restrict__ Wchi, const __nv_bfloat16* __restrict__ Wclo,
    const float* __restrict__ W1tail,
    const float* __restrict__ b1, const float* __restrict__ b2,
    const float* __restrict__ bc1, const float* __restrict__ Wcc,
    float* __restrict__ aggF, float* __restrict__ aggC)
{
    extern __shared__ uint32_t smw[];
    uint32_t* sThi = smw;
    uint32_t* sTlo = smw + ET_LO;
    uint32_t* sW   = smw + EW_B;
    float* sCD   = (float*)(smw + E_MISC);
    float* sDist = sCD + 384;
    float* sEatt = sDist + 128;
    float* sCW   = sEatt + 128;
    int* sIdxC   = (int*)(sCW + 128);
    int* sIdxR   = sIdxC + 128;
    float* sB1   = (float*)(sIdxR + 128);   // 128
    float* sWd   = sB1 + 128;               // 128
    float* sWe   = sWd + 128;               // 128

    const int tid = threadIdx.x;
    const int lane = tid & 31, wid = tid >> 5;
    const int wr = wid & 3, wc = wid >> 2;
    const int g = lane >> 2, t = lane & 3;

    if (tid < 128) {
        int e = blockIdx.x * 128 + tid;
        int r = eidx[e], c = eidx[EE + e];
        sIdxR[tid] = r; sIdxC[tid] = c;
        float dx = coords[r * 3 + 0] - coords[c * 3 + 0];
        float dy = coords[r * 3 + 1] - coords[c * 3 + 1];
        float dz = coords[r * 3 + 2] - coords[c * 3 + 2];
        sCD[tid * 3 + 0] = dx; sCD[tid * 3 + 1] = dy; sCD[tid * 3 + 2] = dz;
        sDist[tid] = dx * dx + dy * dy + dz * dz;
        sEatt[tid] = eattr[e];
    } else if (tid < 256) {
        int c = tid - 128;
        sB1[c] = b1[c];
        sWd[c] = W1tail[c];
        sWe[c] = W1tail[128 + c];
    }
    __syncthreads();

    // stage-1 replacement: t = silu(P1[col] + P2[row] + dist*w256 + ea*w257 + b1)
    for (int i = tid; i < 4096; i += 512) {
        int e = i >> 5, q = i & 31;
        float4 a = *(const float4*)&P1[(size_t)sIdxC[e] * HH + q * 4];
        float4 b = *(const float4*)&P2[(size_t)sIdxR[e] * HH + q * 4];
        float d = sDist[e], ea = sEatt[e];
        int c0 = q * 4;
        float t0 = silu_f(a.x + b.x + d * sWd[c0]     + ea * sWe[c0]     + sB1[c0]);
        float t1 = silu_f(a.y + b.y + d * sWd[c0 + 1] + ea * sWe[c0 + 1] + sB1[c0 + 1]);
        float t2 = silu_f(a.z + b.z + d * sWd[c0 + 2] + ea * sWe[c0 + 2] + sB1[c0 + 2]);
        float t3 = silu_f(a.w + b.w + d * sWd[c0 + 3] + ea * sWe[c0 + 3] + sB1[c0 + 3]);
        uint32_t h2, l2, h2b, l2b;
        split2(t0, t1, h2, l2); split2(t2, t3, h2b, l2b);
        int w = e * LDT + q * 2;
        *(uint2*)&sThi[w] = make_uint2(h2, h2b);
        *(uint2*)&sTlo[w] = make_uint2(l2, l2b);
    }
    __syncthreads();

    float acc[2][4][4];

    // -------- stage 2: ef = silu(t @ W2 + b2); RED aggregate; store ef (hi only) --------
    ZERO_ACC(acc);
    wgemm_bf16(W2hi, W2lo, 128, 4, sThi, sTlo, LDT, sW, tid, acc);
    #pragma unroll
    for (int cf = 0; cf < 4; ++cf) {
        int c0 = wc * 32 + cf * 8 + 2 * t;
        float b2a = __ldg(&b2[c0]), b2b = __ldg(&b2[c0 + 1]);
        #pragma unroll
        for (int rf = 0; rf < 2; ++rf) {
            int r0 = wr * 32 + rf * 16 + g;
            float v00 = silu_f(acc[rf][cf][0] + b2a);
            float v01 = silu_f(acc[rf][cf][1] + b2b);
            float v10 = silu_f(acc[rf][cf][2] + b2a);
            float v11 = silu_f(acc[rf][cf][3] + b2b);
            red2(&aggF[(size_t)sIdxC[r0] * HH + c0], v00, v01);
            red2(&aggF[(size_t)sIdxC[r0 + 8] * HH + c0], v10, v11);
            int w0 = r0 * LDT + wc * 16 + cf * 4 + t;
            sThi[w0] = bf16pack(v00, v01);
            sThi[w0 + 8 * LDT] = bf16pack(v10, v11);
        }
    }
    __syncthreads();

    // -------- stage 3 (pure bf16): cw = silu(ef @ Wc1 + bc1) @ Wcc --------
    ZERO_ACC(acc);
    wgemm_bf16_1t(Wchi, 128, 4, sThi, LDT, sW, tid, acc);
    if (tid < 128) sCW[tid] = 0.f;
    __syncthreads();
    #pragma unroll
    for (int rf = 0; rf < 2; ++rf) {
        float pa = 0.f, pb = 0.f;
        #pragma unroll
        for (int cf = 0; cf < 4; ++cf) {
            int c0 = wc * 32 + cf * 8 + 2 * t;
            float ba = __ldg(&bc1[c0]), bb = __ldg(&bc1[c0 + 1]);
            float wa = __ldg(&Wcc[c0]), wb = __ldg(&Wcc[c0 + 1]);
            pa = fmaf(silu_f(acc[rf][cf][0] + ba), wa, pa);
            pa = fmaf(silu_f(acc[rf][cf][1] + bb), wb, pa);
            pb = fmaf(silu_f(acc[rf][cf][2] + ba), wa, pb);
            pb = fmaf(silu_f(acc[rf][cf][3] + bb), wb, pb);
        }
        pa += __shfl_xor_sync(0xffffffffu, pa, 1);
        pa += __shfl_xor_sync(0xffffffffu, pa, 2);
        pb += __shfl_xor_sync(0xffffffffu, pb, 1);
        pb += __shfl_xor_sync(0xffffffffu, pb, 2);
        if (t == 0) {
            int r0 = wr * 32 + rf * 16 + g;
            atomicAdd(&sCW[r0], pa);
            atomicAdd(&sCW[r0 + 8], pb);
        }
    }
    __syncthreads();
    if (tid < 128) {
        float cw = sCW[tid];
        int cn = sIdxC[tid];
        atomicAdd(&aggC[cn * 3 + 0], sCD[tid * 3 + 0] * cw);
        atomicAdd(&aggC[cn * 3 + 1], sCD[tid * 3 + 1] * cw);
        atomicAdd(&aggC[cn * 3 + 2], sCD[tid * 3 + 2] * cw);
    }
}

// ================= node update + fused next-layer precompute =================
__global__ __launch_bounds__(512, 1) void node_kernel(
    float* __restrict__ h, float* __restrict__ coords,
    const float* __restrict__ aggF, const float* __restrict__ aggC,
    const float* __restrict__ cnt,
    const __nv_bfloat16* __restrict__ W1hi, const __nv_bfloat16* __restrict__ W1lo,
    const __nv_bfloat16* __restrict__ W2hi, const __nv_bfloat16* __restrict__ W2lo,
    const float* __restrict__ b1, const float* __restrict__ b2,
    const __nv_bfloat16* __restrict__ nx1hi, const __nv_bfloat16* __restrict__ nx1lo,
    float* __restrict__ P1, float* __restrict__ P2, int do_pre)
{
    extern __shared__ uint32_t smw[];
    uint32_t* sXhi = smw;
    uint32_t* sXlo = smw + NX_LO;
    uint32_t* sThi = smw;
    uint32_t* sTlo = smw + NT_LO;
    uint32_t* sW   = smw + NW_B;

    const int tid = threadIdx.x;
    const int n0 = blockIdx.x * 128;
    const int lane = tid & 31, wid = tid >> 5;
    const int wr = wid & 3, wc = wid >> 2;
    const int g = lane >> 2, t = lane & 3;

    for (int i = tid; i < 4096; i += 512) {
        int e = i >> 5, q = i & 31;
        int n = n0 + e;
        float4 a = make_float4(0.f, 0.f, 0.f, 0.f), b = a;
        if (n < NN) {
            a = *(const float4*)&h[(size_t)n * HH + q * 4];
            b = *(const float4*)&aggF[(size_t)n * HH + q * 4];
        }
        uint32_t h2, l2, h2b, l2b;
        split2(a.x, a.y, h2, l2); split2(a.z, a.w, h2b, l2b);
        int w = e * LDX + q * 2;
        *(uint2*)&sXhi[w] = make_uint2(h2, h2b);
        *(uint2*)&sXlo[w] = make_uint2(l2, l2b);
        split2(b.x, b.y, h2, l2); split2(b.z, b.w, h2b, l2b);
        *(uint2*)&sXhi[w + 64] = make_uint2(h2, h2b);
        *(uint2*)&sXlo[w + 64] = make_uint2(l2, l2b);
    }
    __syncthreads();

    float acc[2][4][4];
    ZERO_ACC(acc);
    wgemm_bf16(W1hi, W1lo, 256, 8, sXhi, sXlo, LDX, sW, tid, acc);
    #pragma unroll
    for (int cf = 0; cf < 4; ++cf) {
        int c0 = wc * 32 + cf * 8 + 2 * t;
        float b1a = __ldg(&b1[c0]), b1b = __ldg(&b1[c0 + 1]);
        #pragma unroll
        for (int rf = 0; rf < 2; ++rf) {
            int r0 = wr * 32 + rf * 16 + g;
            float t00 = silu_f(acc[rf][cf][0] + b1a);
            float t01 = silu_f(acc[rf][cf][1] + b1b);
            float t10 = silu_f(acc[rf][cf][2] + b1a);
            float t11 = silu_f(acc[rf][cf][3] + b1b);
            uint32_t h2, l2;
            int w0 = r0 * LDT + wc * 16 + cf * 4 + t;
            split2(t00, t01, h2, l2); sThi[w0] = h2; sTlo[w0] = l2;
            split2(t10, t11, h2, l2); sThi[w0 + 8 * LDT] = h2; sTlo[w0 + 8 * LDT] = l2;
        }
    }
    __syncthreads();

    ZERO_ACC(acc);
    wgemm_bf16(W2hi, W2lo, 128, 4, sThi, sTlo, LDT, sW, tid, acc);
    #pragma unroll
    for (int cf = 0; cf < 4; ++cf) {
        int c0 = wc * 32 + cf * 8 + 2 * t;
        float b2a = __ldg(&b2[c0]), b2b = __ldg(&b2[c0 + 1]);
        #pragma unroll
        for (int rf = 0; rf < 2; ++rf) {
            int r0 = wr * 32 + rf * 16 + g;
            int na = n0 + r0, nb = n0 + r0 + 8;
            float v00 = 0.f, v01 = 0.f, v10 = 0.f, v11 = 0.f;
            if (na < NN) {
                size_t idx = (size_t)na * HH + c0;
                v00 = h[idx] + acc[rf][cf][0] + b2a;
                v01 = h[idx + 1] + acc[rf][cf][1] + b2b;
                h[idx] = v00; h[idx + 1] = v01;
            }
            if (nb < NN) {
                size_t idx = (size_t)nb * HH + c0;
                v10 = h[idx] + acc[rf][cf][2] + b2a;
                v11 = h[idx + 1] + acc[rf][cf][3] + b2b;
                h[idx] = v10; h[idx + 1] = v11;
            }
            if (do_pre) {
                uint32_t h2, l2;
                int w0 = r0 * LDT + wc * 16 + cf * 4 + t;
                split2(v00, v01, h2, l2); sThi[w0] = h2; sTlo[w0] = l2;
                split2(v10, v11, h2, l2); sThi[w0 + 8 * LDT] = h2; sTlo[w0 + 8 * LDT] = l2;
            }
        }
    }

    if (tid < 384) {
        int n = n0 + tid / 3, d = tid % 3;
        if (n < NN) {
            float cv = cnt[n];
            cv = cv < 1.f ? 1.f : cv;
            coords[n * 3 + d] += aggC[n * 3 + d] / cv;
        }
    }

    if (do_pre) {
        __syncthreads();
        ZERO_ACC(acc);
        wgemm_bf16(nx1hi, nx1lo, 256, 4, sThi, sTlo, LDT, sW, tid, acc);
        #pragma unroll
        for (int cf = 0; cf < 4; ++cf) {
            int c0 = wc * 32 + cf * 8 + 2 * t;
            #pragma unroll
            for (int rf = 0; rf < 2; ++rf) {
                int r0 = wr * 32 + rf * 16 + g;
                int na = n0 + r0, nb = n0 + r0 + 8;
                if (na < NN) {
                    P1[(size_t)na * HH + c0]     = acc[rf][cf][0];
                    P1[(size_t)na * HH + c0 + 1] = acc[rf][cf][1];
                }
                if (nb < NN) {
                    P1[(size_t)nb * HH + c0]     = acc[rf][cf][2];
                    P1[(size_t)nb * HH + c0 + 1] = acc[rf][cf][3];
                }
            }
        }
        ZERO_ACC(acc);
        wgemm_bf16(nx1hi + 128, nx1lo + 128, 256, 4, sThi, sTlo, LDT, sW, tid, acc);
        #pragma unroll
        for (int cf = 0; cf < 4; ++cf) {
            int c0 = wc * 32 + cf * 8 + 2 * t;
            #pragma unroll
            for (int rf = 0; rf < 2; ++rf) {
                int r0 = wr * 32 + rf * 16 + g;
                int na = n0 + r0, nb = n0 + r0 + 8;
                if (na < NN) {
                    P2[(size_t)na * HH + c0]     = acc[rf][cf][0];
                    P2[(size_t)na * HH + c0 + 1] = acc[rf][cf][1];
                }
                if (nb < NN) {
                    P2[(size_t)nb * HH + c0]     = acc[rf][cf][2];
                    P2[(size_t)nb * HH + c0 + 1] = acc[rf][cf][3];
                }
            }
        }
    }
}

// ================= FFMA linear (small embeddings only) =================
__device__ __forceinline__ void bgemm(const float* __restrict__ gW,
                                      const float* sIn, int ldi,
                                      float* sW, int K, int tid,
                                      float acc[4][8])
{
    const int nI = tid & 15;
    const int eI = tid >> 4;
    for (int k0 = 0; k0 < K; k0 += 32) {
        const int kc = (K - k0) < 32 ? (K - k0) : 32;
        for (int i = tid; i < (kc << 5); i += 256) {
            int r = i >> 5, q = i & 31;
            *(float4*)&sW[r * 128 + q * 4] =
                *(const float4*)&gW[(size_t)(k0 + r) * 128 + q * 4];
        }
        __syncthreads();
        const float* x0p = sIn + (eI * 4 + 0) * ldi + k0;
        const float* x1p = sIn + (eI * 4 + 1) * ldi + k0;
        const float* x2p = sIn + (eI * 4 + 2) * ldi + k0;
        const float* x3p = sIn + (eI * 4 + 3) * ldi + k0;
        for (int r = 0; r < kc; ++r) {
            float xv[4] = {x0p[r], x1p[r], x2p[r], x3p[r]};
            float4 wa = *(const float4*)&sW[r * 128 + nI * 8];
            float4 wb = *(const float4*)&sW[r * 128 + nI * 8 + 4];
            float wv[8] = {wa.x, wa.y, wa.z, wa.w, wb.x, wb.y, wb.z, wb.w};
            #pragma unroll
            for (int a = 0; a < 4; ++a)
                #pragma unroll
                for (int c = 0; c < 8; ++c)
                    acc[a][c] = fmaf(xv[a], wv[c], acc[a][c]);
        }
        __syncthreads();
    }
}

static const int LIN_SMEM = (64 * 260 + 32 * 128) * 4;

__global__ __launch_bounds__(256, 1) void linear_kernel(
    const float* __restrict__ Xg, int K,
    const float* __restrict__ W, const float* __restrict__ b,
    float* __restrict__ Y, int nrows)
{
    extern __shared__ float smf[];
    float* sX = smf;
    float* sW = sX + 64 * 260;
    int tid = threadIdx.x;
    int n0 = blockIdx.x * 64;
    int kq = K >> 2;
    for (int i = tid; i < 64 * kq; i += 256) {
        int e = i / kq, q = i % kq;
        int n = n0 + e;
        float4 v = make_float4(0.f, 0.f, 0.f, 0.f);
        if (n < nrows) v = *(const float4*)&Xg[(size_t)n * K + q * 4];
        *(float4*)&sX[e * 260 + q * 4] = v;
    }
    __syncthreads();
    float acc[4][8];
    #pragma unroll
    for (int a = 0; a < 4; ++a)
        #pragma unroll
        for (int c = 0; c < 8; ++c) acc[a][c] = 0.f;
    bgemm(W, sX, 260, sW, K, tid, acc);
    int nI = tid & 15, eI = tid >> 4;
    float bias[8];
    #pragma unroll
    for (int c = 0; c < 8; ++c) bias[c] = __ldg(&b[nI * 8 + c]);
    #pragma unroll
    for (int a = 0; a < 4; ++a) {
        int n = n0 + eI * 4 + a;
        if (n < nrows) {
            #pragma unroll
            for (int c = 0; c < 8; ++c)
                Y[(size_t)n * 128 + nI * 8 + c] = acc[a][c] + bias[c];
        }
    }
}

// ================= host launcher =================
extern "C" void kernel_launch(void* const* d_in, const int* in_sizes, int n_in,
                              void* d_out, int out_size)
{
    (void)in_sizes; (void)n_in; (void)out_size;
    const float* h_in   = (const float*)d_in[0];
    const float* coords = (const float*)d_in[1];
    const float* eattr  = (const float*)d_in[2];
    const float* embiW  = (const float*)d_in[3];
    const float* embib  = (const float*)d_in[4];
    const float* emboW  = (const float*)d_in[5];
    const float* embob  = (const float*)d_in[6];
    const float* eW1    = (const float*)d_in[7];
    const float* eb1    = (const float*)d_in[8];
    const float* eW2    = (const float*)d_in[9];
    const float* eb2    = (const float*)d_in[10];
    const float* cW1    = (const float*)d_in[11];
    const float* cb1    = (const float*)d_in[12];
    const float* cWc    = (const float*)d_in[13];
    const float* nW1    = (const float*)d_in[14];
    const float* nb1    = (const float*)d_in[15];
    const float* nW2    = (const float*)d_in[16];
    const float* nb2    = (const float*)d_in[17];
    const int*   eidx   = (const int*)d_in[18];
    float* out = (float*)d_out;

    cudaFuncSetAttribute(edge_kernel,   cudaFuncAttributeMaxDynamicSharedMemorySize, EDGE_SMEM);
    cudaFuncSetAttribute(node_kernel,   cudaFuncAttributeMaxDynamicSharedMemorySize, NODE_SMEM);
    cudaFuncSetAttribute(pre_kernel,    cudaFuncAttributeMaxDynamicSharedMemorySize, PRE_SMEM);
    cudaFuncSetAttribute(linear_kernel, cudaFuncAttributeMaxDynamicSharedMemorySize, LIN_SMEM);

    float *p_h, *p_coords, *p_aggF, *p_aggC, *p_cnt, *p_P1, *p_P2;
    cudaGetSymbolAddress((void**)&p_h, g_h);
    cudaGetSymbolAddress((void**)&p_coords, g_coords);
    cudaGetSymbolAddress((void**)&p_aggF, g_aggF);
    cudaGetSymbolAddress((void**)&p_aggC, g_aggC);
    cudaGetSymbolAddress((void**)&p_cnt, g_cnt);
    cudaGetSymbolAddress((void**)&p_P1, g_P1);
    cudaGetSymbolAddress((void**)&p_P2, g_P2);

    __nv_bfloat16 *pe1h, *pe1l, *pe2h, *pe2l, *pch, *pcl, *pn1h, *pn1l, *pn2h, *pn2l;
    cudaGetSymbolAddress((void**)&pe1h, g_eW1hi); cudaGetSymbolAddress((void**)&pe1l, g_eW1lo);
    cudaGetSymbolAddress((void**)&pe2h, g_eW2hi); cudaGetSymbolAddress((void**)&pe2l, g_eW2lo);
    cudaGetSymbolAddress((void**)&pch,  g_cW1hi); cudaGetSymbolAddress((void**)&pcl,  g_cW1lo);
    cudaGetSymbolAddress((void**)&pn1h, g_nW1hi); cudaGetSymbolAddress((void**)&pn1l, g_nW1lo);
    cudaGetSymbolAddress((void**)&pn2h, g_nW2hi); cudaGetSymbolAddress((void**)&pn2l, g_nW2lo);

    const int NB_N = (NN + 127) / 128;   // 391
    const int NB_E = EE / 128;           // 6250
    const int NB_L = (NN + 63) / 64;     // 782

    prep_kernel<<<LL * 128, 256>>>(eW1, pe1h, pe1l, K1, 256);
    prep_kernel<<<LL * 64, 256>>>(eW2, pe2h, pe2l, HH, 128);
    prep_kernel<<<LL * 64, 256>>>(cW1, pch, pcl, HH, 128);
    prep_kernel<<<LL * 128, 256>>>(nW1, pn1h, pn1l, 2 * HH, 256);
    prep_kernel<<<LL * 64, 256>>>(nW2, pn2h, pn2l, HH, 128);

    zero_kernel<<<256, 256>>>(p_cnt, NN);
    count_kernel<<<(EE + 255) / 256, 256>>>(eidx, p_cnt);

    linear_kernel<<<NB_L, 256, LIN_SMEM>>>(h_in, INCH, embiW, embib, p_h, NN);
    copy_kernel<<<(NN * 3 + 255) / 256, 256>>>(coords, p_coords, NN * 3);

    pre_kernel<<<NB_N, 512, PRE_SMEM>>>(p_h, pe1h, pe1l, p_P1, p_P2);

    for (int l = 0; l < LL; ++l) {
        zero_kernel<<<512, 256>>>(p_aggF, NN * HH);
        zero_kernel<<<256, 256>>>(p_aggC, NN * 3);
        edge_kernel<<<NB_E, 512, EDGE_SMEM>>>(
            p_P1, p_P2, p_coords, eattr, eidx,
            pe2h + (size_t)l * 128 * 128, pe2l + (size_t)l * 128 * 128,
            pch  + (size_t)l * 128 * 128, pcl  + (size_t)l * 128 * 128,
            eW1 + (size_t)l * K1 * HH + 256 * HH,
            eb1 + (size_t)l * HH, eb2 + (size_t)l * HH,
            cb1 + (size_t)l * HH, cWc + (size_t)l * HH,
            p_aggF, p_aggC);
        int do_pre = (l + 1 < LL) ? 1 : 0;
        const __nv_bfloat16* nx1h = pe1h + (size_t)(do_pre ? l + 1 : l) * 128 * 256;
        const __nv_bfloat16* nx1l = pe1l + (size_t)(do_pre ? l + 1 : l) * 128 * 256;
        node_kernel<<<NB_N, 512, NODE_SMEM>>>(
            p_h, p_coords, p_aggF, p_aggC, p_cnt,
            pn1h + (size_t)l * 128 * 256, pn1l + (size_t)l * 128 * 256,
            pn2h + (size_t)l * 128 * 128, pn2l + (size_t)l * 128 * 128,
            nb1 + (size_t)l * HH, nb2 + (size_t)l * HH,
            nx1h, nx1l, p_P1, p_P2, do_pre);
    }

    linear_kernel<<<NB_L, 256, LIN_SMEM>>>(p_h, HH, emboW, embob, out, NN);
    copy_kernel<<<(NN * 3 + 255) / 256, 256>>>(p_coords, out + (size_t)NN * HH, NN * 3);
}

// round 17
// speedup vs baseline: 1.1654x; 1.0622x over previous
#include <cuda_runtime.h>
#include <cuda_bf16.h>
#include <cstdint>

#define NN 50000
#define EE 800000
#define HH 128
#define INCH 64
#define LL 4
#define K1 258

// word strides (uint32 units)
#define LDX 132   // node sX: 264 bf16/row
#define LDT 68    // sT / pre sX: 136 bf16/row
#define LDB 20    // sW: 40 bf16/row

// ================= scratch (__device__ globals; no allocation) =================
__device__ float g_h[(size_t)NN * HH];
__device__ float g_coords[(size_t)NN * 3];
__device__ float g_aggF[(size_t)NN * HH];
__device__ float g_aggC[(size_t)NN * 3];
__device__ float g_cnt[NN];
__device__ float g_P1[(size_t)NN * HH];
__device__ float g_P2[(size_t)NN * HH];
// pre-transposed + bf16-split weights: [L][n=128][k]
__device__ __align__(16) __nv_bfloat16 g_eW1hi[(size_t)LL * 128 * 256];
__device__ __align__(16) __nv_bfloat16 g_eW1lo[(size_t)LL * 128 * 256];
__device__ __align__(16) __nv_bfloat16 g_eW2hi[(size_t)LL * 128 * 128];
__device__ __align__(16) __nv_bfloat16 g_eW2lo[(size_t)LL * 128 * 128];
__device__ __align__(16) __nv_bfloat16 g_cW1hi[(size_t)LL * 128 * 128];
__device__ __align__(16) __nv_bfloat16 g_cW1lo[(size_t)LL * 128 * 128];
__device__ __align__(16) __nv_bfloat16 g_nW1hi[(size_t)LL * 128 * 256];
__device__ __align__(16) __nv_bfloat16 g_nW1lo[(size_t)LL * 128 * 256];
__device__ __align__(16) __nv_bfloat16 g_nW2hi[(size_t)LL * 128 * 128];
__device__ __align__(16) __nv_bfloat16 g_nW2lo[(size_t)LL * 128 * 128];

__device__ __forceinline__ float silu_f(float x) {
    return x * __fdividef(1.f, 1.f + __expf(-x));
}

__device__ __forceinline__ uint32_t bf16pack(float f0, float f1) {
    uint32_t d;
    asm("cvt.rn.bf16x2.f32 %0, %1, %2;" : "=r"(d) : "f"(f1), "f"(f0));
    return d;
}
__device__ __forceinline__ void split2(float f0, float f1, uint32_t& h2, uint32_t& l2) {
    h2 = bf16pack(f0, f1);
    float h0 = __uint_as_float(h2 << 16);
    float h1 = __uint_as_float(h2 & 0xffff0000u);
    l2 = bf16pack(f0 - h0, f1 - h1);
}

__device__ __forceinline__ void cp_async16(uint32_t dst, const void* src) {
    asm volatile("cp.async.ca.shared.global [%0], [%1], 16;" :: "r"(dst), "l"(src));
}
#define CP_COMMIT() asm volatile("cp.async.commit_group;" ::: "memory")
#define CP_WAIT0()  asm volatile("cp.async.wait_group 0;" ::: "memory")

__device__ __forceinline__ void ldsm4(uint32_t* r, uint32_t addr) {
    asm volatile("ldmatrix.sync.aligned.m8n8.x4.shared.b16 {%0,%1,%2,%3}, [%4];"
                 : "=r"(r[0]), "=r"(r[1]), "=r"(r[2]), "=r"(r[3]) : "r"(addr));
}

__device__ __forceinline__ void red2(float* p, float a, float b) {
    asm volatile("red.global.add.v2.f32 [%0], {%1,%2};" :: "l"(p), "f"(a), "f"(b) : "memory");
}

#define MMA_BF16(d, a0, a1, a2, a3, b0, b1) \
    asm volatile("mma.sync.aligned.m16n8k16.row.col.f32.bf16.bf16.f32 " \
                 "{%0,%1,%2,%3}, {%4,%5,%6,%7}, {%8,%9}, {%0,%1,%2,%3};" \
                 : "+f"((d)[0]), "+f"((d)[1]), "+f"((d)[2]), "+f"((d)[3]) \
                 : "r"(a0), "r"(a1), "r"(a2), "r"(a3), "r"(b0), "r"(b1))

#define ZERO_ACC(acc) do { \
    _Pragma("unroll") for (int _r = 0; _r < 2; ++_r) \
    _Pragma("unroll") for (int _c = 0; _c < 4; ++_c) \
    _Pragma("unroll") for (int _q = 0; _q < 4; ++_q) acc[_r][_c][_q] = 0.f; } while (0)

// =================== bf16x3 warp-tiled GEMM (128 x 128, 16 warps, ldmatrix) ===================
__device__ __forceinline__ void wgemm_bf16(
    const __nv_bfloat16* __restrict__ gHi, const __nv_bfloat16* __restrict__ gLo,
    int Kg, int nch,
    const uint32_t* sInHi, const uint32_t* sInLo, int ldw,
    uint32_t* sW, int tid, float acc[2][4][4])
{
    const int lane = tid & 31, wid = tid >> 5;
    const int wr = wid & 3, wc = wid >> 2;
    const int n = tid >> 2, seg = tid & 3;

    uint32_t swb = (uint32_t)__cvta_generic_to_shared(sW);
    uint32_t dst_hi = swb + (n * LDB + seg * 4) * 4;
    uint32_t dst_lo = dst_hi + 2560 * 4;
    const __nv_bfloat16* src_h = gHi + (size_t)n * Kg + seg * 8;
    const __nv_bfloat16* src_l = gLo + (size_t)n * Kg + seg * 8;

    cp_async16(dst_hi, src_h);
    cp_async16(dst_lo, src_l);
    CP_COMMIT(); CP_WAIT0();
    __syncthreads();

    const uint32_t aOff = (uint32_t)(wr * 32 + (lane & 15)) * (uint32_t)ldw * 4u
                        + (uint32_t)(lane >> 4) * 16u;
    const uint32_t aHi0 = (uint32_t)__cvta_generic_to_shared(sInHi) + aOff;
    const uint32_t aLo0 = (uint32_t)__cvta_generic_to_shared(sInLo) + aOff;
    const uint32_t aRf = (uint32_t)(16 * ldw * 4);
    const uint32_t bOff = (uint32_t)(wc * 32 + ((lane >> 4) << 3) + (lane & 7)) * (LDB * 4u)
                        + (uint32_t)((lane >> 3) & 1) * 16u;

    for (int c = 0; c < nch; ++c) {
        if (c + 1 < nch) {
            uint32_t off = (uint32_t)((c + 1) & 1) * (5120 * 4);
            cp_async16(dst_hi + off, src_h + (c + 1) * 32);
            cp_async16(dst_lo + off, src_l + (c + 1) * 32);
            CP_COMMIT();
        }
        uint32_t bufHiB = swb + (uint32_t)(c & 1) * (5120 * 4) + bOff;
        uint32_t bufLoB = bufHiB + 2560 * 4;
        #pragma unroll
        for (int ks = 0; ks < 2; ++ks) {
            const uint32_t ka4 = (uint32_t)(c * 16 + ks * 8) * 4u;
            uint32_t ah[2][4], al[2][4], bh[2][4], bl[2][4];
            ldsm4(ah[0], aHi0 + ka4);
            ldsm4(ah[1], aHi0 + ka4 + aRf);
            ldsm4(al[0], aLo0 + ka4);
            ldsm4(al[1], aLo0 + ka4 + aRf);
            ldsm4(bh[0], bufHiB + ks * 32);
            ldsm4(bh[1], bufHiB + ks * 32 + 16 * LDB * 4);
            ldsm4(bl[0], bufLoB + ks * 32);
            ldsm4(bl[1], bufLoB + ks * 32 + 16 * LDB * 4);
            #pragma unroll
            for (int cf = 0; cf < 4; ++cf) {
                const int p = cf >> 1, ix = (cf & 1) * 2;
                #pragma unroll
                for (int rf = 0; rf < 2; ++rf)
                    MMA_BF16(acc[rf][cf], ah[rf][0], ah[rf][1], ah[rf][2], ah[rf][3],
                             bl[p][ix], bl[p][ix + 1]);
            }
            #pragma unroll
            for (int cf = 0; cf < 4; ++cf) {
                const int p = cf >> 1, ix = (cf & 1) * 2;
                #pragma unroll
                for (int rf = 0; rf < 2; ++rf)
                    MMA_BF16(acc[rf][cf], al[rf][0], al[rf][1], al[rf][2], al[rf][3],
                             bh[p][ix], bh[p][ix + 1]);
            }
            #pragma unroll
            for (int cf = 0; cf < 4; ++cf) {
                const int p = cf >> 1, ix = (cf & 1) * 2;
                #pragma unroll
                for (int rf = 0; rf < 2; ++rf)
                    MMA_BF16(acc[rf][cf], ah[rf][0], ah[rf][1], ah[rf][2], ah[rf][3],
                             bh[p][ix], bh[p][ix + 1]);
            }
        }
        if (c + 1 < nch) CP_WAIT0();
        __syncthreads();
    }
}

// 2-term variant: A plain bf16 (hi only); B compensated. D += Ah*Bl + Ah*Bh.
__device__ __forceinline__ void wgemm_bf16_2t(
    const __nv_bfloat16* __restrict__ gHi, const __nv_bfloat16* __restrict__ gLo,
    int Kg, int nch,
    const uint32_t* sInHi, int ldw,
    uint32_t* sW, int tid, float acc[2][4][4])
{
    const int lane = tid & 31, wid = tid >> 5;
    const int wr = wid & 3, wc = wid >> 2;
    const int n = tid >> 2, seg = tid & 3;

    uint32_t swb = (uint32_t)__cvta_generic_to_shared(sW);
    uint32_t dst_hi = swb + (n * LDB + seg * 4) * 4;
    uint32_t dst_lo = dst_hi + 2560 * 4;
    const __nv_bfloat16* src_h = gHi + (size_t)n * Kg + seg * 8;
    const __nv_bfloat16* src_l = gLo + (size_t)n * Kg + seg * 8;

    cp_async16(dst_hi, src_h);
    cp_async16(dst_lo, src_l);
    CP_COMMIT(); CP_WAIT0();
    __syncthreads();

    const uint32_t aOff = (uint32_t)(wr * 32 + (lane & 15)) * (uint32_t)ldw * 4u
                        + (uint32_t)(lane >> 4) * 16u;
    const uint32_t aHi0 = (uint32_t)__cvta_generic_to_shared(sInHi) + aOff;
    const uint32_t aRf = (uint32_t)(16 * ldw * 4);
    const uint32_t bOff = (uint32_t)(wc * 32 + ((lane >> 4) << 3) + (lane & 7)) * (LDB * 4u)
                        + (uint32_t)((lane >> 3) & 1) * 16u;

    for (int c = 0; c < nch; ++c) {
        if (c + 1 < nch) {
            uint32_t off = (uint32_t)((c + 1) & 1) * (5120 * 4);
            cp_async16(dst_hi + off, src_h + (c + 1) * 32);
            cp_async16(dst_lo + off, src_l + (c + 1) * 32);
            CP_COMMIT();
        }
        uint32_t bufHiB = swb + (uint32_t)(c & 1) * (5120 * 4) + bOff;
        uint32_t bufLoB = bufHiB + 2560 * 4;
        #pragma unroll
        for (int ks = 0; ks < 2; ++ks) {
            const uint32_t ka4 = (uint32_t)(c * 16 + ks * 8) * 4u;
            uint32_t ah[2][4], bh[2][4], bl[2][4];
            ldsm4(ah[0], aHi0 + ka4);
            ldsm4(ah[1], aHi0 + ka4 + aRf);
            ldsm4(bh[0], bufHiB + ks * 32);
            ldsm4(bh[1], bufHiB + ks * 32 + 16 * LDB * 4);
            ldsm4(bl[0], bufLoB + ks * 32);
            ldsm4(bl[1], bufLoB + ks * 32 + 16 * LDB * 4);
            #pragma unroll
            for (int cf = 0; cf < 4; ++cf) {
                const int p = cf >> 1, ix = (cf & 1) * 2;
                #pragma unroll
                for (int rf = 0; rf < 2; ++rf)
                    MMA_BF16(acc[rf][cf], ah[rf][0], ah[rf][1], ah[rf][2], ah[rf][3],
                             bl[p][ix], bl[p][ix + 1]);
            }
            #pragma unroll
            for (int cf = 0; cf < 4; ++cf) {
                const int p = cf >> 1, ix = (cf & 1) * 2;
                #pragma unroll
                for (int rf = 0; rf < 2; ++rf)
                    MMA_BF16(acc[rf][cf], ah[rf][0], ah[rf][1], ah[rf][2], ah[rf][3],
                             bh[p][ix], bh[p][ix + 1]);
            }
        }
        if (c + 1 < nch) CP_WAIT0();
        __syncthreads();
    }
}

// pure-bf16 single-term variant: A hi only, B hi only. D += Ah*Bh.
__device__ __forceinline__ void wgemm_bf16_1t(
    const __nv_bfloat16* __restrict__ gHi,
    int Kg, int nch,
    const uint32_t* sInHi, int ldw,
    uint32_t* sW, int tid, float acc[2][4][4])
{
    const int lane = tid & 31, wid = tid >> 5;
    const int wr = wid & 3, wc = wid >> 2;
    const int n = tid >> 2, seg = tid & 3;

    uint32_t swb = (uint32_t)__cvta_generic_to_shared(sW);
    uint32_t dst_hi = swb + (n * LDB + seg * 4) * 4;
    const __nv_bfloat16* src_h = gHi + (size_t)n * Kg + seg * 8;

    cp_async16(dst_hi, src_h);
    CP_COMMIT(); CP_WAIT0();
    __syncthreads();

    const uint32_t aOff = (uint32_t)(wr * 32 + (lane & 15)) * (uint32_t)ldw * 4u
                        + (uint32_t)(lane >> 4) * 16u;
    const uint32_t aHi0 = (uint32_t)__cvta_generic_to_shared(sInHi) + aOff;
    const uint32_t aRf = (uint32_t)(16 * ldw * 4);
    const uint32_t bOff = (uint32_t)(wc * 32 + ((lane >> 4) << 3) + (lane & 7)) * (LDB * 4u)
                        + (uint32_t)((lane >> 3) & 1) * 16u;

    for (int c = 0; c < nch; ++c) {
        if (c + 1 < nch) {
            uint32_t off = (uint32_t)((c + 1) & 1) * (5120 * 4);
            cp_async16(dst_hi + off, src_h + (c + 1) * 32);
            CP_COMMIT();
        }
        uint32_t bufHiB = swb + (uint32_t)(c & 1) * (5120 * 4) + bOff;
        #pragma unroll
        for (int ks = 0; ks < 2; ++ks) {
            const uint32_t ka4 = (uint32_t)(c * 16 + ks * 8) * 4u;
            uint32_t ah[2][4], bh[2][4];
            ldsm4(ah[0], aHi0 + ka4);
            ldsm4(ah[1], aHi0 + ka4 + aRf);
            ldsm4(bh[0], bufHiB + ks * 32);
            ldsm4(bh[1], bufHiB + ks * 32 + 16 * LDB * 4);
            #pragma unroll
            for (int cf = 0; cf < 4; ++cf) {
                const int p = cf >> 1, ix = (cf & 1) * 2;
                #pragma unroll
                for (int rf = 0; rf < 2; ++rf)
                    MMA_BF16(acc[rf][cf], ah[rf][0], ah[rf][1], ah[rf][2], ah[rf][3],
                             bh[p][ix], bh[p][ix + 1]);
            }
        }
        if (c + 1 < nch) CP_WAIT0();
        __syncthreads();
    }
}

// ================= weight prep: transpose + bf16 split =================
__global__ void prep_kernel(const float* __restrict__ W,
                            __nv_bfloat16* __restrict__ hi,
                            __nv_bfloat16* __restrict__ lo, int Kin, int Kg)
{
    int i = blockIdx.x * blockDim.x + threadIdx.x;
    int tot = LL * 128 * Kg;
    if (i >= tot) return;
    int l = i / (128 * Kg);
    int rem = i - l * 128 * Kg;
    int nn = rem / Kg, k = rem - nn * Kg;
    float v = W[(size_t)l * Kin * 128 + (size_t)k * 128 + nn];
    __nv_bfloat16 h = __float2bfloat16(v);
    hi[i] = h;
    lo[i] = __float2bfloat16(v - __bfloat162float(h));
}

// ================= small utility kernels =================
__global__ void zero_kernel(float* __restrict__ p, int n) {
    for (int i = blockIdx.x * blockDim.x + threadIdx.x; i < n; i += gridDim.x * blockDim.x)
        p[i] = 0.f;
}
__global__ void copy_kernel(const float* __restrict__ src, float* __restrict__ dst, int n) {
    int i = blockIdx.x * blockDim.x + threadIdx.x;
    if (i < n) dst[i] = src[i];
}
__global__ void count_kernel(const int* __restrict__ eidx, float* __restrict__ cnt) {
    int e = blockIdx.x * blockDim.x + threadIdx.x;
    if (e < EE) atomicAdd(&cnt[eidx[EE + e]], 1.f);
}

// ================= SMEM layouts =================
#define NX_LO 16896
#define NT_LO 8704
#define NW_B  33792
static const int NODE_SMEM = 44032 * 4;            // 176128 B
static const int PRE_SMEM = 27648 * 4;             // 110592 B
#define ET_LO 8704
#define EW_B  17408
#define E_MISC 27648
static const int EDGE_SMEM = (E_MISC + 1408) * 4;  // 116224 B

// ================= layer-0 node precompute: P1 = h@W1a, P2 = h@W1b =================
__global__ __launch_bounds__(512, 1) void pre_kernel(
    const float* __restrict__ hcur,
    const __nv_bfloat16* __restrict__ W1hi, const __nv_bfloat16* __restrict__ W1lo,
    float* __restrict__ P1, float* __restrict__ P2)
{
    extern __shared__ uint32_t smw[];
    uint32_t* sXhi = smw;
    uint32_t* sXlo = smw + ET_LO;
    uint32_t* sW   = smw + EW_B;

    const int tid = threadIdx.x;
    const int n0 = blockIdx.x * 128;
    const int lane = tid & 31, wid = tid >> 5;
    const int wr = wid & 3, wc = wid >> 2;
    const int g = lane >> 2, t = lane & 3;

    for (int i = tid; i < 4096; i += 512) {
        int e = i >> 5, q = i & 31;
        int n = n0 + e;
        float4 a = make_float4(0.f, 0.f, 0.f, 0.f);
        if (n < NN) a = *(const float4*)&hcur[(size_t)n * HH + q * 4];
        uint32_t h2, l2, h2b, l2b;
        split2(a.x, a.y, h2, l2); split2(a.z, a.w, h2b, l2b);
        int w = e * LDT + q * 2;
        *(uint2*)&sXhi[w] = make_uint2(h2, h2b);
        *(uint2*)&sXlo[w] = make_uint2(l2, l2b);
    }
    __syncthreads();

    float acc[2][4][4];
    ZERO_ACC(acc);
    wgemm_bf16(W1hi, W1lo, 256, 4, sXhi, sXlo, LDT, sW, tid, acc);
    #pragma unroll
    for (int cf = 0; cf < 4; ++cf) {
        int c0 = wc * 32 + cf * 8 + 2 * t;
        #pragma unroll
        for (int rf = 0; rf < 2; ++rf) {
            int r0 = wr * 32 + rf * 16 + g;
            int na = n0 + r0, nb = n0 + r0 + 8;
            if (na < NN) {
                P1[(size_t)na * HH + c0]     = acc[rf][cf][0];
                P1[(size_t)na * HH + c0 + 1] = acc[rf][cf][1];
            }
            if (nb < NN) {
                P1[(size_t)nb * HH + c0]     = acc[rf][cf][2];
                P1[(size_t)nb * HH + c0 + 1] = acc[rf][cf][3];
            }
        }
    }
    ZERO_ACC(acc);
    wgemm_bf16(W1hi + 128, W1lo + 128, 256, 4, sXhi, sXlo, LDT, sW, tid, acc);
    #pragma unroll
    for (int cf = 0; cf < 4; ++cf) {
        int c0 = wc * 32 + cf * 8 + 2 * t;
        #pragma unroll
        for (int rf = 0; rf < 2; ++rf) {
            int r0 = wr * 32 + rf * 16 + g;
            int na = n0 + r0, nb = n0 + r0 + 8;
            if (na < NN) {
                P2[(size_t)na * HH + c0]     = acc[rf][cf][0];
                P2[(size_t)na * HH + c0 + 1] = acc[rf][cf][1];
            }
            if (nb < NN) {
                P2[(size_t)nb * HH + c0]     = acc[rf][cf][2];
                P2[(size_t)nb * HH + c0 + 1] = acc[rf][cf][3];
            }
        }
    }
}

// ================= fused edge kernel (128 edges/CTA, 512 threads) =================
__global__ __launch_bounds__(512, 1) void edge_kernel(
    const float* __restrict__ P1, const float* __restrict__ P2,
    const float* __restrict__ coords,
    const float* __restrict__ eattr, const int* __restrict__ eidx,
    const __nv_bfloat16* __restrict__ W2hi, const __nv_bfloat16* __restrict__ W2lo,
    const __nv_bfloat16* __restrict__ Wchi, const __nv_bfloat16* __restrict__ Wclo,
    const float* __restrict__ W1tail,
    const float* __restrict__ b1, const float* __restrict__ b2,
    const float* __restrict__ bc1, const float* __restrict__ Wcc,
    float* __restrict__ aggF, float* __restrict__ aggC)
{
    extern __shared__ uint32_t smw[];
    uint32_t* sThi = smw;
    uint32_t* sW   = smw + EW_B;
    float* sCD   = (float*)(smw + E_MISC);
    float* sDist = sCD + 384;
    float* sEatt = sDist + 128;
    float* sCW   = sEatt + 128;
    int* sIdxC   = (int*)(sCW + 128);
    int* sIdxR   = sIdxC + 128;
    float* sB1   = (float*)(sIdxR + 128);   // 128
    float* sWd   = sB1 + 128;               // 128
    float* sWe   = sWd + 128;               // 128

    const int tid = threadIdx.x;
    const int lane = tid & 31, wid = tid >> 5;
    const int wr = wid & 3, wc = wid >> 2;
    const int g = lane >> 2, t = lane & 3;

    if (tid < 128) {
        int e = blockIdx.x * 128 + tid;
        int r = eidx[e], c = eidx[EE + e];
        sIdxR[tid] = r; sIdxC[tid] = c;
        float dx = coords[r * 3 + 0] - coords[c * 3 + 0];
        float dy = coords[r * 3 + 1] - coords[c * 3 + 1];
        float dz = coords[r * 3 + 2] - coords[c * 3 + 2];
        sCD[tid * 3 + 0] = dx; sCD[tid * 3 + 1] = dy; sCD[tid * 3 + 2] = dz;
        sDist[tid] = dx * dx + dy * dy + dz * dz;
        sEatt[tid] = eattr[e];
    } else if (tid < 256) {
        int c = tid - 128;
        sB1[c] = b1[c];
        sWd[c] = W1tail[c];
        sWe[c] = W1tail[128 + c];
    }
    __syncthreads();

    // stage-1 replacement: t = silu(P1[col] + P2[row] + dist*w256 + ea*w257 + b1)
    // (plain bf16 store only — stage-2 is 2-term, A-lo not needed)
    for (int i = tid; i < 4096; i += 512) {
        int e = i >> 5, q = i & 31;
        float4 a = *(const float4*)&P1[(size_t)sIdxC[e] * HH + q * 4];
        float4 b = *(const float4*)&P2[(size_t)sIdxR[e] * HH + q * 4];
        float d = sDist[e], ea = sEatt[e];
        int c0 = q * 4;
        float t0 = silu_f(a.x + b.x + d * sWd[c0]     + ea * sWe[c0]     + sB1[c0]);
        float t1 = silu_f(a.y + b.y + d * sWd[c0 + 1] + ea * sWe[c0 + 1] + sB1[c0 + 1]);
        float t2 = silu_f(a.z + b.z + d * sWd[c0 + 2] + ea * sWe[c0 + 2] + sB1[c0 + 2]);
        float t3 = silu_f(a.w + b.w + d * sWd[c0 + 3] + ea * sWe[c0 + 3] + sB1[c0 + 3]);
        int w = e * LDT + q * 2;
        *(uint2*)&sThi[w] = make_uint2(bf16pack(t0, t1), bf16pack(t2, t3));
    }
    __syncthreads();

    float acc[2][4][4];

    // -------- stage 2 (2-term): ef = silu(t @ W2 + b2); RED aggregate; store ef --------
    ZERO_ACC(acc);
    wgemm_bf16_2t(W2hi, W2lo, 128, 4, sThi, LDT, sW, tid, acc);
    #pragma unroll
    for (int cf = 0; cf < 4; ++cf) {
        int c0 = wc * 32 + cf * 8 + 2 * t;
        float b2a = __ldg(&b2[c0]), b2b = __ldg(&b2[c0 + 1]);
        #pragma unroll
        for (int rf = 0; rf < 2; ++rf) {
            int r0 = wr * 32 + rf * 16 + g;
            float v00 = silu_f(acc[rf][cf][0] + b2a);
            float v01 = silu_f(acc[rf][cf][1] + b2b);
            float v10 = silu_f(acc[rf][cf][2] + b2a);
            float v11 = silu_f(acc[rf][cf][3] + b2b);
            red2(&aggF[(size_t)sIdxC[r0] * HH + c0], v00, v01);
            red2(&aggF[(size_t)sIdxC[r0 + 8] * HH + c0], v10, v11);
            int w0 = r0 * LDT + wc * 16 + cf * 4 + t;
            sThi[w0] = bf16pack(v00, v01);
            sThi[w0 + 8 * LDT] = bf16pack(v10, v11);
        }
    }
    __syncthreads();

    // -------- stage 3 (pure bf16): cw = silu(ef @ Wc1 + bc1) @ Wcc --------
    ZERO_ACC(acc);
    wgemm_bf16_1t(Wchi, 128, 4, sThi, LDT, sW, tid, acc);
    if (tid < 128) sCW[tid] = 0.f;
    __syncthreads();
    #pragma unroll
    for (int rf = 0; rf < 2; ++rf) {
        float pa = 0.f, pb = 0.f;
        #pragma unroll
        for (int cf = 0; cf < 4; ++cf) {
            int c0 = wc * 32 + cf * 8 + 2 * t;
            float ba = __ldg(&bc1[c0]), bb = __ldg(&bc1[c0 + 1]);
            float wa = __ldg(&Wcc[c0]), wb = __ldg(&Wcc[c0 + 1]);
            pa = fmaf(silu_f(acc[rf][cf][0] + ba), wa, pa);
            pa = fmaf(silu_f(acc[rf][cf][1] + bb), wb, pa);
            pb = fmaf(silu_f(acc[rf][cf][2] + ba), wa, pb);
            pb = fmaf(silu_f(acc[rf][cf][3] + bb), wb, pb);
        }
        pa += __shfl_xor_sync(0xffffffffu, pa, 1);
        pa += __shfl_xor_sync(0xffffffffu, pa, 2);
        pb += __shfl_xor_sync(0xffffffffu, pb, 1);
        pb += __shfl_xor_sync(0xffffffffu, pb, 2);
        if (t == 0) {
            int r0 = wr * 32 + rf * 16 + g;
            atomicAdd(&sCW[r0], pa);
            atomicAdd(&sCW[r0 + 8], pb);
        }
    }
    __syncthreads();
    if (tid < 128) {
        float cw = sCW[tid];
        int cn = sIdxC[tid];
        atomicAdd(&aggC[cn * 3 + 0], sCD[tid * 3 + 0] * cw);
        atomicAdd(&aggC[cn * 3 + 1], sCD[tid * 3 + 1] * cw);
        atomicAdd(&aggC[cn * 3 + 2], sCD[tid * 3 + 2] * cw);
    }
}

// ================= node update + fused next-layer precompute =================
__global__ __launch_bounds__(512, 1) void node_kernel(
    float* __restrict__ h, float* __restrict__ coords,
    const float* __restrict__ aggF, const float* __restrict__ aggC,
    const float* __restrict__ cnt,
    const __nv_bfloat16* __restrict__ W1hi, const __nv_bfloat16* __restrict__ W1lo,
    const __nv_bfloat16* __restrict__ W2hi, const __nv_bfloat16* __restrict__ W2lo,
    const float* __restrict__ b1, const float* __restrict__ b2,
    const __nv_bfloat16* __restrict__ nx1hi, const __nv_bfloat16* __restrict__ nx1lo,
    float* __restrict__ P1, float* __restrict__ P2, int do_pre)
{
    extern __shared__ uint32_t smw[];
    uint32_t* sXhi = smw;
    uint32_t* sXlo = smw + NX_LO;
    uint32_t* sThi = smw;
    uint32_t* sTlo = smw + NT_LO;
    uint32_t* sW   = smw + NW_B;

    const int tid = threadIdx.x;
    const int n0 = blockIdx.x * 128;
    const int lane = tid & 31, wid = tid >> 5;
    const int wr = wid & 3, wc = wid >> 2;
    const int g = lane >> 2, t = lane & 3;

    for (int i = tid; i < 4096; i += 512) {
        int e = i >> 5, q = i & 31;
        int n = n0 + e;
        float4 a = make_float4(0.f, 0.f, 0.f, 0.f), b = a;
        if (n < NN) {
            a = *(const float4*)&h[(size_t)n * HH + q * 4];
            b = *(const float4*)&aggF[(size_t)n * HH + q * 4];
        }
        uint32_t h2, l2, h2b, l2b;
        split2(a.x, a.y, h2, l2); split2(a.z, a.w, h2b, l2b);
        int w = e * LDX + q * 2;
        *(uint2*)&sXhi[w] = make_uint2(h2, h2b);
        *(uint2*)&sXlo[w] = make_uint2(l2, l2b);
        split2(b.x, b.y, h2, l2); split2(b.z, b.w, h2b, l2b);
        *(uint2*)&sXhi[w + 64] = make_uint2(h2, h2b);
        *(uint2*)&sXlo[w + 64] = make_uint2(l2, l2b);
    }
    __syncthreads();

    float acc[2][4][4];
    ZERO_ACC(acc);
    wgemm_bf16(W1hi, W1lo, 256, 8, sXhi, sXlo, LDX, sW, tid, acc);
    #pragma unroll
    for (int cf = 0; cf < 4; ++cf) {
        int c0 = wc * 32 + cf * 8 + 2 * t;
        float b1a = __ldg(&b1[c0]), b1b = __ldg(&b1[c0 + 1]);
        #pragma unroll
        for (int rf = 0; rf < 2; ++rf) {
            int r0 = wr * 32 + rf * 16 + g;
            float t00 = silu_f(acc[rf][cf][0] + b1a);
            float t01 = silu_f(acc[rf][cf][1] + b1b);
            float t10 = silu_f(acc[rf][cf][2] + b1a);
            float t11 = silu_f(acc[rf][cf][3] + b1b);
            uint32_t h2, l2;
            int w0 = r0 * LDT + wc * 16 + cf * 4 + t;
            split2(t00, t01, h2, l2); sThi[w0] = h2; sTlo[w0] = l2;
            split2(t10, t11, h2, l2); sThi[w0 + 8 * LDT] = h2; sTlo[w0 + 8 * LDT] = l2;
        }
    }
    __syncthreads();

    ZERO_ACC(acc);
    wgemm_bf16(W2hi, W2lo, 128, 4, sThi, sTlo, LDT, sW, tid, acc);
    #pragma unroll
    for (int cf = 0; cf < 4; ++cf) {
        int c0 = wc * 32 + cf * 8 + 2 * t;
        float b2a = __ldg(&b2[c0]), b2b = __ldg(&b2[c0 + 1]);
        #pragma unroll
        for (int rf = 0; rf < 2; ++rf) {
            int r0 = wr * 32 + rf * 16 + g;
            int na = n0 + r0, nb = n0 + r0 + 8;
            float v00 = 0.f, v01 = 0.f, v10 = 0.f, v11 = 0.f;
            if (na < NN) {
                size_t idx = (size_t)na * HH + c0;
                v00 = h[idx] + acc[rf][cf][0] + b2a;
                v01 = h[idx + 1] + acc[rf][cf][1] + b2b;
                h[idx] = v00; h[idx + 1] = v01;
            }
            if (nb < NN) {
                size_t idx = (size_t)nb * HH + c0;
                v10 = h[idx] + acc[rf][cf][2] + b2a;
                v11 = h[idx + 1] + acc[rf][cf][3] + b2b;
                h[idx] = v10; h[idx + 1] = v11;
            }
            if (do_pre) {
                uint32_t h2, l2;
                int w0 = r0 * LDT + wc * 16 + cf * 4 + t;
                split2(v00, v01, h2, l2); sThi[w0] = h2; sTlo[w0] = l2;
                split2(v10, v11, h2, l2); sThi[w0 + 8 * LDT] = h2; sTlo[w0 + 8 * LDT] = l2;
            }
        }
    }

    if (tid < 384) {
        int n = n0 + tid / 3, d = tid % 3;
        if (n < NN) {
            float cv = cnt[n];
            cv = cv < 1.f ? 1.f : cv;
            coords[n * 3 + d] += aggC[n * 3 + d] / cv;
        }
    }

    if (do_pre) {
        __syncthreads();
        ZERO_ACC(acc);
        wgemm_bf16(nx1hi, nx1lo, 256, 4, sThi, sTlo, LDT, sW, tid, acc);
        #pragma unroll
        for (int cf = 0; cf < 4; ++cf) {
            int c0 = wc * 32 + cf * 8 + 2 * t;
            #pragma unroll
            for (int rf = 0; rf < 2; ++rf) {
                int r0 = wr * 32 + rf * 16 + g;
                int na = n0 + r0, nb = n0 + r0 + 8;
                if (na < NN) {
                    P1[(size_t)na * HH + c0]     = acc[rf][cf][0];
                    P1[(size_t)na * HH + c0 + 1] = acc[rf][cf][1];
                }
                if (nb < NN) {
                    P1[(size_t)nb * HH + c0]     = acc[rf][cf][2];
                    P1[(size_t)nb * HH + c0 + 1] = acc[rf][cf][3];
                }
            }
        }
        ZERO_ACC(acc);
        wgemm_bf16(nx1hi + 128, nx1lo + 128, 256, 4, sThi, sTlo, LDT, sW, tid, acc);
        #pragma unroll
        for (int cf = 0; cf < 4; ++cf) {
            int c0 = wc * 32 + cf * 8 + 2 * t;
            #pragma unroll
            for (int rf = 0; rf < 2; ++rf) {
                int r0 = wr * 32 + rf * 16 + g;
                int na = n0 + r0, nb = n0 + r0 + 8;
                if (na < NN) {
                    P2[(size_t)na * HH + c0]     = acc[rf][cf][0];
                    P2[(size_t)na * HH + c0 + 1] = acc[rf][cf][1];
                }
                if (nb < NN) {
                    P2[(size_t)nb * HH + c0]     = acc[rf][cf][2];
                    P2[(size_t)nb * HH + c0 + 1] = acc[rf][cf][3];
                }
            }
        }
    }
}

// ================= FFMA linear (small embeddings only) =================
__device__ __forceinline__ void bgemm(const float* __restrict__ gW,
                                      const float* sIn, int ldi,
                                      float* sW, int K, int tid,
                                      float acc[4][8])
{
    const int nI = tid & 15;
    const int eI = tid >> 4;
    for (int k0 = 0; k0 < K; k0 += 32) {
        const int kc = (K - k0) < 32 ? (K - k0) : 32;
        for (int i = tid; i < (kc << 5); i += 256) {
            int r = i >> 5, q = i & 31;
            *(float4*)&sW[r * 128 + q * 4] =
                *(const float4*)&gW[(size_t)(k0 + r) * 128 + q * 4];
        }
        __syncthreads();
        const float* x0p = sIn + (eI * 4 + 0) * ldi + k0;
        const float* x1p = sIn + (eI * 4 + 1) * ldi + k0;
        const float* x2p = sIn + (eI * 4 + 2) * ldi + k0;
        const float* x3p = sIn + (eI * 4 + 3) * ldi + k0;
        for (int r = 0; r < kc; ++r) {
            float xv[4] = {x0p[r], x1p[r], x2p[r], x3p[r]};
            float4 wa = *(const float4*)&sW[r * 128 + nI * 8];
            float4 wb = *(const float4*)&sW[r * 128 + nI * 8 + 4];
            float wv[8] = {wa.x, wa.y, wa.z, wa.w, wb.x, wb.y, wb.z, wb.w};
            #pragma unroll
            for (int a = 0; a < 4; ++a)
                #pragma unroll
                for (int c = 0; c < 8; ++c)
                    acc[a][c] = fmaf(xv[a], wv[c], acc[a][c]);
        }
        __syncthreads();
    }
}

static const int LIN_SMEM = (64 * 260 + 32 * 128) * 4;

__global__ __launch_bounds__(256, 1) void linear_kernel(
    const float* __restrict__ Xg, int K,
    const float* __restrict__ W, const float* __restrict__ b,
    float* __restrict__ Y, int nrows)
{
    extern __shared__ float smf[];
    float* sX = smf;
    float* sW = sX + 64 * 260;
    int tid = threadIdx.x;
    int n0 = blockIdx.x * 64;
    int kq = K >> 2;
    for (int i = tid; i < 64 * kq; i += 256) {
        int e = i / kq, q = i % kq;
        int n = n0 + e;
        float4 v = make_float4(0.f, 0.f, 0.f, 0.f);
        if (n < nrows) v = *(const float4*)&Xg[(size_t)n * K + q * 4];
        *(float4*)&sX[e * 260 + q * 4] = v;
    }
    __syncthreads();
    float acc[4][8];
    #pragma unroll
    for (int a = 0; a < 4; ++a)
        #pragma unroll
        for (int c = 0; c < 8; ++c) acc[a][c] = 0.f;
    bgemm(W, sX, 260, sW, K, tid, acc);
    int nI = tid & 15, eI = tid >> 4;
    float bias[8];
    #pragma unroll
    for (int c = 0; c < 8; ++c) bias[c] = __ldg(&b[nI * 8 + c]);
    #pragma unroll
    for (int a = 0; a < 4; ++a) {
        int n = n0 + eI * 4 + a;
        if (n < nrows) {
            #pragma unroll
            for (int c = 0; c < 8; ++c)
                Y[(size_t)n * 128 + nI * 8 + c] = acc[a][c] + bias[c];
        }
    }
}

// ================= host launcher =================
extern "C" void kernel_launch(void* const* d_in, const int* in_sizes, int n_in,
                              void* d_out, int out_size)
{
    (void)in_sizes; (void)n_in; (void)out_size;
    const float* h_in   = (const float*)d_in[0];
    const float* coords = (const float*)d_in[1];
    const float* eattr  = (const float*)d_in[2];
    const float* embiW  = (const float*)d_in[3];
    const float* embib  = (const float*)d_in[4];
    const float* emboW  = (const float*)d_in[5];
    const float* embob  = (const float*)d_in[6];
    const float* eW1    = (const float*)d_in[7];
    const float* eb1    = (const float*)d_in[8];
    const float* eW2    = (const float*)d_in[9];
    const float* eb2    = (const float*)d_in[10];
    const float* cW1    = (const float*)d_in[11];
    const float* cb1    = (const float*)d_in[12];
    const float* cWc    = (const float*)d_in[13];
    const float* nW1    = (const float*)d_in[14];
    const float* nb1    = (const float*)d_in[15];
    const float* nW2    = (const float*)d_in[16];
    const float* nb2    = (const float*)d_in[17];
    const int*   eidx   = (const int*)d_in[18];
    float* out = (float*)d_out;

    cudaFuncSetAttribute(edge_kernel,   cudaFuncAttributeMaxDynamicSharedMemorySize, EDGE_SMEM);
    cudaFuncSetAttribute(node_kernel,   cudaFuncAttributeMaxDynamicSharedMemorySize, NODE_SMEM);
    cudaFuncSetAttribute(pre_kernel,    cudaFuncAttributeMaxDynamicSharedMemorySize, PRE_SMEM);
    cudaFuncSetAttribute(linear_kernel, cudaFuncAttributeMaxDynamicSharedMemorySize, LIN_SMEM);

    float *p_h, *p_coords, *p_aggF, *p_aggC, *p_cnt, *p_P1, *p_P2;
    cudaGetSymbolAddress((void**)&p_h, g_h);
    cudaGetSymbolAddress((void**)&p_coords, g_coords);
    cudaGetSymbolAddress((void**)&p_aggF, g_aggF);
    cudaGetSymbolAddress((void**)&p_aggC, g_aggC);
    cudaGetSymbolAddress((void**)&p_cnt, g_cnt);
    cudaGetSymbolAddress((void**)&p_P1, g_P1);
    cudaGetSymbolAddress((void**)&p_P2, g_P2);

    __nv_bfloat16 *pe1h, *pe1l, *pe2h, *pe2l, *pch, *pcl, *pn1h, *pn1l, *pn2h, *pn2l;
    cudaGetSymbolAddress((void**)&pe1h, g_eW1hi); cudaGetSymbolAddress((void**)&pe1l, g_eW1lo);
    cudaGetSymbolAddress((void**)&pe2h, g_eW2hi); cudaGetSymbolAddress((void**)&pe2l, g_eW2lo);
    cudaGetSymbolAddress((void**)&pch,  g_cW1hi); cudaGetSymbolAddress((void**)&pcl,  g_cW1lo);
    cudaGetSymbolAddress((void**)&pn1h, g_nW1hi); cudaGetSymbolAddress((void**)&pn1l, g_nW1lo);
    cudaGetSymbolAddress((void**)&pn2h, g_nW2hi); cudaGetSymbolAddress((void**)&pn2l, g_nW2lo);

    const int NB_N = (NN + 127) / 128;   // 391
    const int NB_E = EE / 128;           // 6250
    const int NB_L = (NN + 63) / 64;     // 782

    prep_kernel<<<LL * 128, 256>>>(eW1, pe1h, pe1l, K1, 256);
    prep_kernel<<<LL * 64, 256>>>(eW2, pe2h, pe2l, HH, 128);
    prep_kernel<<<LL * 64, 256>>>(cW1, pch, pcl, HH, 128);
    prep_kernel<<<LL * 128, 256>>>(nW1, pn1h, pn1l, 2 * HH, 256);
    prep_kernel<<<LL * 64, 256>>>(nW2, pn2h, pn2l, HH, 128);

    zero_kernel<<<256, 256>>>(p_cnt, NN);
    count_kernel<<<(EE + 255) / 256, 256>>>(eidx, p_cnt);

    linear_kernel<<<NB_L, 256, LIN_SMEM>>>(h_in, INCH, embiW, embib, p_h, NN);
    copy_kernel<<<(NN * 3 + 255) / 256, 256>>>(coords, p_coords, NN * 3);

    pre_kernel<<<NB_N, 512, PRE_SMEM>>>(p_h, pe1h, pe1l, p_P1, p_P2);

    for (int l = 0; l < LL; ++l) {
        zero_kernel<<<512, 256>>>(p_aggF, NN * HH);
        zero_kernel<<<256, 256>>>(p_aggC, NN * 3);
        edge_kernel<<<NB_E, 512, EDGE_SMEM>>>(
            p_P1, p_P2, p_coords, eattr, eidx,
            pe2h + (size_t)l * 128 * 128, pe2l + (size_t)l * 128 * 128,
            pch  + (size_t)l * 128 * 128, pcl  + (size_t)l * 128 * 128,
            eW1 + (size_t)l * K1 * HH + 256 * HH,
            eb1 + (size_t)l * HH, eb2 + (size_t)l * HH,
            cb1 + (size_t)l * HH, cWc + (size_t)l * HH,
            p_aggF, p_aggC);
        int do_pre = (l + 1 < LL) ? 1 : 0;
        const __nv_bfloat16* nx1h = pe1h + (size_t)(do_pre ? l + 1 : l) * 128 * 256;
        const __nv_bfloat16* nx1l = pe1l + (size_t)(do_pre ? l + 1 : l) * 128 * 256;
        node_kernel<<<NB_N, 512, NODE_SMEM>>>(
            p_h, p_coords, p_aggF, p_aggC, p_cnt,
            pn1h + (size_t)l * 128 * 256, pn1l + (size_t)l * 128 * 256,
            pn2h + (size_t)l * 128 * 128, pn2l + (size_t)l * 128 * 128,
            nb1 + (size_t)l * HH, nb2 + (size_t)l * HH,
            nx1h, nx1l, p_P1, p_P2, do_pre);
    }

    linear_kernel<<<NB_L, 256, LIN_SMEM>>>(p_h, HH, emboW, embob, out, NN);
    copy_kernel<<<(NN * 3 + 255) / 256, 256>>>(p_coords, out + (size_t)NN * HH, NN * 3);
}